// round 13
// baseline (speedup 1.0000x reference)
#include <cuda_runtime.h>
#include <cuda_fp16.h>
#include <cuda_bf16.h>
#include <cstdint>
#include <cstddef>

// ---------------------------------------------------------------------------
// Problem constants
// ---------------------------------------------------------------------------
#define T_STEPS 2048
#define BATCH   256
#define IN_DIM  64
#define H_DIM   1280
#define H4      320
#define HID     160
#define GATES   640
#define O_DIM   32
#define MTOT    (T_STEPS*BATCH)   // 524288
#define CHUNK   65536             // rows per pipeline chunk (8 chunks)

// ---------------------------------------------------------------------------
// Device scratch — keep total under ~2.5GB (aarch64 .bss shadow reloc limit)
// ---------------------------------------------------------------------------
__device__ __align__(256) __nv_bfloat16 gIhi [(size_t)CHUNK * IN_DIM];
__device__ __align__(256) __nv_bfloat16 gIlo [(size_t)CHUNK * IN_DIM];
__device__ __align__(256) __nv_bfloat16 gX1hi[(size_t)CHUNK * H_DIM];
__device__ __align__(256) __nv_bfloat16 gX1lo[(size_t)CHUNK * H_DIM];
__device__ __align__(256) __nv_bfloat16 gX2hi[(size_t)CHUNK * H4];
__device__ __align__(256) __nv_bfloat16 gX2lo[(size_t)CHUNK * H4];
__device__ __align__(256) float gGX  [(size_t)MTOT * GATES];            // 1.34GB
__device__ __align__(256) float gHout[(size_t)MTOT * HID];              // 335MB
__device__ __align__(256) __nv_bfloat16 gW1hi[H_DIM * IN_DIM];
__device__ __align__(256) __nv_bfloat16 gW1lo[H_DIM * IN_DIM];
__device__ __align__(256) __nv_bfloat16 gW2hi[H4 * H_DIM];
__device__ __align__(256) __nv_bfloat16 gW2lo[H4 * H_DIM];
__device__ __align__(256) __nv_bfloat16 gWihi[GATES * H4];
__device__ __align__(256) __nv_bfloat16 gWilo[GATES * H4];
__device__ __align__(256) uint2 gWt2[40 * GATES];   // W_hh fp16 pack for scan

// ---------------------------------------------------------------------------
// PTX helpers — base-ISA only (sm_80+ features, legal on .target sm_103)
// ---------------------------------------------------------------------------
__device__ __forceinline__ uint32_t smem_u32(const void* p) {
    uint32_t a;
    asm("{ .reg .u64 t; cvta.to.shared.u64 t, %1; cvt.u32.u64 %0, t; }"
        : "=r"(a) : "l"(p));
    return a;
}
__device__ __forceinline__ void cp_async16(uint32_t dst, const void* src) {
    asm volatile("cp.async.cg.shared.global [%0], [%1], 16;"
                 :: "r"(dst), "l"(src) : "memory");
}
#define CP_COMMIT() asm volatile("cp.async.commit_group;" ::: "memory")
#define CP_WAIT(n)  asm volatile("cp.async.wait_group %0;" :: "n"(n) : "memory")

__device__ __forceinline__ void ldsm_x4(uint32_t* r, uint32_t addr) {
    asm volatile("ldmatrix.sync.aligned.m8n8.x4.shared.b16 {%0,%1,%2,%3}, [%4];"
        : "=r"(r[0]), "=r"(r[1]), "=r"(r[2]), "=r"(r[3]) : "r"(addr));
}
__device__ __forceinline__ void mma16816(float* d, const uint32_t* a,
                                         const uint32_t* b) {
    asm volatile("mma.sync.aligned.m16n8k16.row.col.f32.bf16.bf16.f32 "
        "{%0,%1,%2,%3}, {%4,%5,%6,%7}, {%8,%9}, {%0,%1,%2,%3};"
        : "+f"(d[0]), "+f"(d[1]), "+f"(d[2]), "+f"(d[3])
        : "r"(a[0]), "r"(a[1]), "r"(a[2]), "r"(a[3]), "r"(b[0]), "r"(b[1]));
}

// ---------------------------------------------------------------------------
// SMEM layout for mma_gemm, CTA tile 128x320 (BN=320):
//   buf b (b=0,1) at b*57344:
//     Ahi [128][32]bf16 @+0 (8K)      Alo @+8192
//     Bhi [320][32]bf16 @+16384 (20K) Blo @+36864
//   stage (epilogue, union): float [128][324] = 165888 B @0
//   sBias: 320 floats @165888
// Swizzle: 16B chunk c (0..3) of a 64B row -> c ^ ((row>>1)&3).
// ng step of +16 rows keeps (row>>1)&3 invariant -> swizzled offset += 1024.
// ---------------------------------------------------------------------------
#define BUF_STRIDE   57344
#define SM_ALO       8192
#define SM_B         16384
#define SM_BLO       20480      // relative to SM_B
#define STG_STRIDE   324
#define SM_BIAS      165888
#define GEMM_SMEM    167424

template <int OUTMODE>   // 0: leaky -> bf16 hi/lo planes; 1: fp32 out (+bias2)
__global__ __launch_bounds__(256, 1)
void mma_gemm(const __nv_bfloat16* __restrict__ Ahi, const __nv_bfloat16* __restrict__ Alo,
              const __nv_bfloat16* __restrict__ Bhi, const __nv_bfloat16* __restrict__ Blo,
              const float* __restrict__ bias, const float* __restrict__ bias2,
              __nv_bfloat16* __restrict__ outHi, __nv_bfloat16* __restrict__ outLo,
              float* __restrict__ outF, int N, int K)
{
    extern __shared__ __align__(128) char smem[];
    const uint32_t sbase = smem_u32(smem);
    const int tid  = threadIdx.x;
    const int lane = tid & 31;
    const int w    = tid >> 5;
    const int warpM = w & 3;        // 0..3 -> M rows [warpM*32, +32)
    const int warpN = w >> 2;       // 0..1 -> N cols [warpN*160, +160)
    const int m0 = blockIdx.y * 128;
    const int n0 = blockIdx.x * 320;

    float* sBias = (float*)(smem + SM_BIAS);
    for (int i = tid; i < 320; i += 256) {
        float bv = bias[n0 + i];
        if (bias2) bv += bias2[n0 + i];
        sBias[i] = bv;
    }

    float acc[2][20][4];
#pragma unroll
    for (int mt = 0; mt < 2; ++mt)
#pragma unroll
        for (int nt = 0; nt < 20; ++nt)
#pragma unroll
            for (int r = 0; r < 4; ++r) acc[mt][nt][r] = 0.f;

    const int NK = K >> 5;

    // A ldmatrix offsets (per mt, per s): proven layout from R12.
    uint32_t offA[2][2];
#pragma unroll
    for (int mt = 0; mt < 2; ++mt)
#pragma unroll
        for (int s = 0; s < 2; ++s) {
            int row = warpM * 32 + mt * 16 + (lane & 15);
            int ch  = s * 2 + (lane >> 4);
            offA[mt][s] = row * 64 + ((ch ^ ((row >> 1) & 3)) << 4);
        }
    // B ldmatrix base offsets (ng=0); per ng add 1024 (16 rows * 64B, phase-safe).
    uint32_t offB0[2];
#pragma unroll
    for (int s = 0; s < 2; ++s) {
        int g   = lane >> 3;
        int row = warpN * 160 + ((g >> 1) << 3) + (lane & 7);
        int ch  = s * 2 + (g & 1);
        offB0[s] = SM_B + row * 64 + ((ch ^ ((row >> 1) & 3)) << 4);
    }

    auto issue_load = [&](int kt) {
        const uint32_t bb = sbase + (uint32_t)(kt & 1) * BUF_STRIDE;
        const size_t kof = (size_t)kt * 32;
#pragma unroll
        for (int j = 0; j < 4; ++j) {           // A: 1024 16B-chunks
            int i = tid + j * 256;
            int plane = i >> 9, row = (i >> 2) & 127, c = i & 3;
            const __nv_bfloat16* src =
                (plane ? Alo : Ahi) + (size_t)(m0 + row) * K + kof + c * 8;
            uint32_t dst = bb + plane * SM_ALO + row * 64 +
                           ((c ^ ((row >> 1) & 3)) << 4);
            cp_async16(dst, src);
        }
#pragma unroll
        for (int j = 0; j < 10; ++j) {          // B: 2560 16B-chunks
            int i = tid + j * 256;
            int plane = (i >= 1280);
            int ii = i - plane * 1280;
            int row = ii >> 2, c = ii & 3;
            const __nv_bfloat16* src =
                (plane ? Blo : Bhi) + (size_t)(n0 + row) * K + kof + c * 8;
            uint32_t dst = bb + SM_B + plane * SM_BLO + row * 64 +
                           ((c ^ ((row >> 1) & 3)) << 4);
            cp_async16(dst, src);
        }
        CP_COMMIT();
    };

    issue_load(0);

    for (int kt = 0; kt < NK; ++kt) {
        const uint32_t bb = sbase + (uint32_t)(kt & 1) * BUF_STRIDE;
        if (kt + 1 < NK) { issue_load(kt + 1); CP_WAIT(1); }
        else             { CP_WAIT(0); }
        __syncthreads();

#pragma unroll
        for (int s = 0; s < 2; ++s) {
            uint32_t ah[2][4], al[2][4];
#pragma unroll
            for (int mt = 0; mt < 2; ++mt) {
                ldsm_x4(ah[mt], bb + offA[mt][s]);
                ldsm_x4(al[mt], bb + SM_ALO + offA[mt][s]);
            }
#pragma unroll
            for (int ng = 0; ng < 10; ++ng) {
                uint32_t bh[4], bl[4];
                uint32_t baddr = bb + offB0[s] + ng * 1024;
                ldsm_x4(bh, baddr);                 // t0,t1=n0-7 k0-15; t2,t3=n8-15
                ldsm_x4(bl, baddr + SM_BLO);
#pragma unroll
                for (int mt = 0; mt < 2; ++mt)
#pragma unroll
                    for (int h = 0; h < 2; ++h) {
                        int nt = ng * 2 + h;
                        mma16816(acc[mt][nt], ah[mt], &bh[h * 2]);
                        mma16816(acc[mt][nt], ah[mt], &bl[h * 2]);
                        mma16816(acc[mt][nt], al[mt], &bh[h * 2]);
                    }
            }
        }
        __syncthreads();
    }

    // ---------------- Epilogue: stage fp32 [128][324], fused writeout -------
    float* stage = (float*)smem;
#pragma unroll
    for (int mt = 0; mt < 2; ++mt)
#pragma unroll
        for (int nt = 0; nt < 20; ++nt) {
            int r = warpM * 32 + mt * 16 + (lane >> 2);
            int c = warpN * 160 + nt * 8 + (lane & 3) * 2;
            stage[r * STG_STRIDE + c]               = acc[mt][nt][0];
            stage[r * STG_STRIDE + c + 1]           = acc[mt][nt][1];
            stage[(r + 8) * STG_STRIDE + c]         = acc[mt][nt][2];
            stage[(r + 8) * STG_STRIDE + c + 1]     = acc[mt][nt][3];
        }
    __syncthreads();

    if (OUTMODE == 0) {
        // 128 rows x 40 groups of 8 cols -> one uint4 per plane per group
#pragma unroll
        for (int j = 0; j < 20; ++j) {
            int idx = tid + j * 256;            // < 5120
            int r  = idx / 40;
            int c0 = (idx - r * 40) * 8;
            __nv_bfloat16 hv[8], lv[8];
#pragma unroll
            for (int q = 0; q < 8; ++q) {
                float v = stage[r * STG_STRIDE + c0 + q] + sBias[c0 + q];
                v = (v > 0.f) ? v : 0.01f * v;
                hv[q] = __float2bfloat16(v);
                lv[q] = __float2bfloat16(v - __bfloat162float(hv[q]));
            }
            size_t go = (size_t)(m0 + r) * N + n0 + c0;
            *(uint4*)(outHi + go) = *(uint4*)hv;
            *(uint4*)(outLo + go) = *(uint4*)lv;
        }
    } else {
        // 128 rows x 80 groups of 4 floats
#pragma unroll
        for (int j = 0; j < 40; ++j) {
            int idx = tid + j * 256;            // < 10240
            int r  = idx / 80;
            int c0 = (idx - r * 80) * 4;
            float4 v;
            v.x = stage[r * STG_STRIDE + c0 + 0] + sBias[c0 + 0];
            v.y = stage[r * STG_STRIDE + c0 + 1] + sBias[c0 + 1];
            v.z = stage[r * STG_STRIDE + c0 + 2] + sBias[c0 + 2];
            v.w = stage[r * STG_STRIDE + c0 + 3] + sBias[c0 + 3];
            *(float4*)(outF + (size_t)(m0 + r) * N + n0 + c0) = v;
        }
    }
}

// ---------------------------------------------------------------------------
// fp32 -> bf16 hi/lo split (vectorized x4)
// ---------------------------------------------------------------------------
__global__ void split_bf16(const float* __restrict__ src,
                           __nv_bfloat16* __restrict__ hi,
                           __nv_bfloat16* __restrict__ lo, long n4)
{
    long i = (long)blockIdx.x * 256 + threadIdx.x;
    if (i >= n4) return;
    float4 v = ((const float4*)src)[i];
    float vs[4] = {v.x, v.y, v.z, v.w};
    __nv_bfloat16 h[4], l[4];
#pragma unroll
    for (int k = 0; k < 4; ++k) {
        h[k] = __float2bfloat16(vs[k]);
        l[k] = __float2bfloat16(vs[k] - __bfloat162float(h[k]));
    }
    *(uint2*)(hi + i * 4) = *(uint2*)h;
    *(uint2*)(lo + i * 4) = *(uint2*)l;
}

// ---------------------------------------------------------------------------
// Scan prep + scan + output GEMV (unchanged from R12)
// ---------------------------------------------------------------------------
__device__ __forceinline__ float2 ffma2(float2 a, float2 b, float2 c) {
    float2 d;
    asm("fma.rn.f32x2 %0, %1, %2, %3;"
        : "=l"(reinterpret_cast<unsigned long long&>(d))
        : "l"(reinterpret_cast<unsigned long long&>(a)),
          "l"(reinterpret_cast<unsigned long long&>(b)),
          "l"(reinterpret_cast<unsigned long long&>(c)));
    return d;
}
__device__ __forceinline__ float fast_sigmoid(float x) {
    return __fdividef(1.f, 1.f + __expf(-x));
}
__device__ __forceinline__ float fast_tanh(float x) {
    return 1.f - __fdividef(2.f, __expf(2.f * x) + 1.f);
}

__global__ void prepack_whh(const float* __restrict__ W)
{
    int i = blockIdx.x * 256 + threadIdx.x;
    if (i >= 40 * GATES) return;
    int p = i / GATES, g = i % GATES;
    const float* wr = W + (size_t)g * HID + p * 4;
    __half2 h01 = __floats2half2_rn(wr[0], wr[1]);
    __half2 h23 = __floats2half2_rn(wr[2], wr[3]);
    uint2 v;
    v.x = *reinterpret_cast<uint32_t*>(&h01);
    v.y = *reinterpret_cast<uint32_t*>(&h23);
    gWt2[(size_t)p * GATES + g] = v;
}

#define SCAN_SMEM (40 * GATES * 8 + 2 * HID * 4 + 2 * GATES * 4)

__global__ __launch_bounds__(GATES, 1)
void lstm_scan(const float* __restrict__ GX, float* __restrict__ Hout)
{
    extern __shared__ unsigned char smem_raw[];
    uint2* sW = reinterpret_cast<uint2*>(smem_raw);
    float* sH = reinterpret_cast<float*>(smem_raw + 40 * GATES * 8);
    float* sG = sH + 2 * HID;

    const int tid  = threadIdx.x;
    const int g    = tid;
    const int row0 = blockIdx.x * 2;

    for (int i = tid; i < 40 * GATES; i += GATES) sW[i] = gWt2[i];
    if (tid < 2 * HID) sH[tid] = 0.f;

    float cc = 0.f;
    const int cr = tid < 2 * HID ? (tid / HID) : 0;
    const int cj = tid < 2 * HID ? (tid - cr * HID) : 0;

    __syncthreads();

    for (int t = 0; t < T_STEPS; ++t) {
        const size_t base = (size_t)t * (BATCH * GATES) + (size_t)row0 * GATES;
        float gx0 = GX[base + g];
        float gx1 = GX[base + GATES + g];

        float2 acc0 = make_float2(0.f, 0.f);
        float2 acc1 = make_float2(0.f, 0.f);
#pragma unroll
        for (int p = 0; p < 40; ++p) {
            uint2 w = sW[p * GATES + g];
            float2 wA = __half22float2(*reinterpret_cast<__half2*>(&w.x));
            float2 wB = __half22float2(*reinterpret_cast<__half2*>(&w.y));
            float4 h0v = *reinterpret_cast<const float4*>(&sH[p * 4]);
            float4 h1v = *reinterpret_cast<const float4*>(&sH[HID + p * 4]);
            acc0 = ffma2(wA, make_float2(h0v.x, h0v.y), acc0);
            acc0 = ffma2(wB, make_float2(h0v.z, h0v.w), acc0);
            acc1 = ffma2(wA, make_float2(h1v.x, h1v.y), acc1);
            acc1 = ffma2(wB, make_float2(h1v.z, h1v.w), acc1);
        }
        float p0 = acc0.x + acc0.y + gx0;
        float p1 = acc1.x + acc1.y + gx1;

        float a0, a1;
        if (g >= 320 && g < 480) { a0 = fast_tanh(p0);    a1 = fast_tanh(p1);    }
        else                     { a0 = fast_sigmoid(p0); a1 = fast_sigmoid(p1); }
        sG[g] = a0;
        sG[GATES + g] = a1;
        __syncthreads();

        if (tid < 2 * HID) {
            const float* Gr = sG + cr * GATES;
            float iv = Gr[cj], fv = Gr[HID + cj], gv = Gr[2 * HID + cj], ov = Gr[3 * HID + cj];
            cc = fv * cc + iv * gv;
            float hv = ov * fast_tanh(cc);
            sH[cr * HID + cj] = hv;
            Hout[(size_t)t * (BATCH * HID) + (size_t)(row0 + cr) * HID + cj] = hv;
        }
        __syncthreads();
    }
}

__global__ __launch_bounds__(256)
void out_gemv(const float* __restrict__ H, const float* __restrict__ W3,
              const float* __restrict__ b3, float* __restrict__ Y)
{
    __shared__ float sW[HID * O_DIM];
    __shared__ float sHr[8 * HID];

    const int tid = threadIdx.x;
    const int r   = tid >> 5;
    const int o   = tid & 31;

    for (int i = tid; i < HID * O_DIM; i += 256) {
        int k = i >> 5, oo = i & 31;
        sW[i] = W3[(size_t)oo * HID + k];
    }
    const size_t mrow0 = (size_t)blockIdx.x * 8;
    for (int i = tid; i < 8 * HID; i += 256)
        sHr[i] = H[mrow0 * HID + i];
    __syncthreads();

    float acc = b3[o];
#pragma unroll 8
    for (int k = 0; k < HID; ++k)
        acc = fmaf(sHr[r * HID + k], sW[k * O_DIM + o], acc);
    Y[(mrow0 + r) * O_DIM + o] = acc;
}

// ---------------------------------------------------------------------------
// Launch
// ---------------------------------------------------------------------------
extern "C" void kernel_launch(void* const* d_in, const int* in_sizes, int n_in,
                              void* d_out, int out_size)
{
    (void)in_sizes; (void)n_in; (void)out_size;
    const float* inputs = (const float*)d_in[0];
    const float* W1     = (const float*)d_in[1];
    const float* b1     = (const float*)d_in[2];
    const float* W2     = (const float*)d_in[3];
    const float* b2     = (const float*)d_in[4];
    const float* W_ih   = (const float*)d_in[5];
    const float* W_hh   = (const float*)d_in[6];
    const float* b_ih   = (const float*)d_in[7];
    const float* b_hh   = (const float*)d_in[8];
    const float* W3     = (const float*)d_in[9];
    const float* b3     = (const float*)d_in[10];
    float* Y = (float*)d_out;

    void *pIh, *pIl, *pX1h, *pX1l, *pX2h, *pX2l, *pGX, *pH;
    void *pW1h, *pW1l, *pW2h, *pW2l, *pWih, *pWil;
    cudaGetSymbolAddress(&pIh,  gIhi);  cudaGetSymbolAddress(&pIl,  gIlo);
    cudaGetSymbolAddress(&pX1h, gX1hi); cudaGetSymbolAddress(&pX1l, gX1lo);
    cudaGetSymbolAddress(&pX2h, gX2hi); cudaGetSymbolAddress(&pX2l, gX2lo);
    cudaGetSymbolAddress(&pGX,  gGX);   cudaGetSymbolAddress(&pH,   gHout);
    cudaGetSymbolAddress(&pW1h, gW1hi); cudaGetSymbolAddress(&pW1l, gW1lo);
    cudaGetSymbolAddress(&pW2h, gW2hi); cudaGetSymbolAddress(&pW2l, gW2lo);
    cudaGetSymbolAddress(&pWih, gWihi); cudaGetSymbolAddress(&pWil, gWilo);

    cudaFuncSetAttribute(mma_gemm<0>, cudaFuncAttributeMaxDynamicSharedMemorySize, GEMM_SMEM);
    cudaFuncSetAttribute(mma_gemm<1>, cudaFuncAttributeMaxDynamicSharedMemorySize, GEMM_SMEM);
    cudaFuncSetAttribute(lstm_scan, cudaFuncAttributeMaxDynamicSharedMemorySize, SCAN_SMEM);

    // Weight splits + scan prepack (once)
    split_bf16<<<H_DIM * IN_DIM / 4 / 256, 256>>>(W1,
        (__nv_bfloat16*)pW1h, (__nv_bfloat16*)pW1l, H_DIM * IN_DIM / 4);
    split_bf16<<<H4 * H_DIM / 4 / 256, 256>>>(W2,
        (__nv_bfloat16*)pW2h, (__nv_bfloat16*)pW2l, H4 * H_DIM / 4);
    split_bf16<<<GATES * H4 / 4 / 256, 256>>>(W_ih,
        (__nv_bfloat16*)pWih, (__nv_bfloat16*)pWil, GATES * H4 / 4);
    prepack_whh<<<(40 * GATES + 255) / 256, 256>>>(W_hh);

    // Chunked batch-parallel pipeline: input split -> fc1 -> fc2 -> gates
    for (int c = 0; c < MTOT / CHUNK; ++c) {
        const float* Ain = inputs + (size_t)c * CHUNK * IN_DIM;
        split_bf16<<<(long)CHUNK * IN_DIM / 4 / 256, 256>>>(Ain,
            (__nv_bfloat16*)pIh, (__nv_bfloat16*)pIl, (long)CHUNK * IN_DIM / 4);

        mma_gemm<0><<<dim3(H_DIM / 320, CHUNK / 128), 256, GEMM_SMEM>>>(
            (__nv_bfloat16*)pIh, (__nv_bfloat16*)pIl,
            (__nv_bfloat16*)pW1h, (__nv_bfloat16*)pW1l,
            b1, nullptr,
            (__nv_bfloat16*)pX1h, (__nv_bfloat16*)pX1l, nullptr, H_DIM, IN_DIM);

        mma_gemm<0><<<dim3(H4 / 320, CHUNK / 128), 256, GEMM_SMEM>>>(
            (__nv_bfloat16*)pX1h, (__nv_bfloat16*)pX1l,
            (__nv_bfloat16*)pW2h, (__nv_bfloat16*)pW2l,
            b2, nullptr,
            (__nv_bfloat16*)pX2h, (__nv_bfloat16*)pX2l, nullptr, H4, H_DIM);

        mma_gemm<1><<<dim3(GATES / 320, CHUNK / 128), 256, GEMM_SMEM>>>(
            (__nv_bfloat16*)pX2h, (__nv_bfloat16*)pX2l,
            (__nv_bfloat16*)pWih, (__nv_bfloat16*)pWil,
            b_ih, b_hh,
            nullptr, nullptr, (float*)pGX + (size_t)c * CHUNK * GATES,
            GATES, H4);
    }

    // Recurrence + output projection
    lstm_scan<<<BATCH / 2, GATES, SCAN_SMEM>>>((float*)pGX, (float*)pH);
    out_gemv<<<MTOT / 8, 256>>>((float*)pH, W3, b3, Y);
}

// round 14
// speedup vs baseline: 1.2103x; 1.2103x over previous
#include <cuda_runtime.h>
#include <cuda_fp16.h>
#include <cuda_bf16.h>
#include <cstdint>
#include <cstddef>

// ---------------------------------------------------------------------------
// Problem constants
// ---------------------------------------------------------------------------
#define T_STEPS 2048
#define BATCH   256
#define IN_DIM  64
#define H_DIM   1280
#define H4      320
#define HID     160
#define GATES   640
#define O_DIM   32
#define MTOT    (T_STEPS*BATCH)   // 524288
#define CHUNK   65536             // rows per pipeline chunk (8 chunks)

// ---------------------------------------------------------------------------
// Device scratch (activations: single fp16 plane; weights: fp16 hi+lo)
// ---------------------------------------------------------------------------
__device__ __align__(256) __half gIq [(size_t)CHUNK * IN_DIM];   // 8.4MB
__device__ __align__(256) __half gX1q[(size_t)CHUNK * H_DIM];    // 168MB
__device__ __align__(256) __half gX2q[(size_t)CHUNK * H4];       // 42MB
__device__ __align__(256) float gGX  [(size_t)MTOT * GATES];     // 1.34GB
__device__ __align__(256) float gHout[(size_t)MTOT * HID];       // 335MB
__device__ __align__(256) __half gW1hi[H_DIM * IN_DIM];
__device__ __align__(256) __half gW1lo[H_DIM * IN_DIM];
__device__ __align__(256) __half gW2hi[H4 * H_DIM];
__device__ __align__(256) __half gW2lo[H4 * H_DIM];
__device__ __align__(256) __half gWihi[GATES * H4];
__device__ __align__(256) __half gWilo[GATES * H4];
__device__ __align__(256) uint2 gWt2[40 * GATES];   // W_hh fp16 pack for scan

// ---------------------------------------------------------------------------
// PTX helpers — base-ISA only (sm_80+ features, legal on .target sm_103)
// ---------------------------------------------------------------------------
__device__ __forceinline__ uint32_t smem_u32(const void* p) {
    uint32_t a;
    asm("{ .reg .u64 t; cvta.to.shared.u64 t, %1; cvt.u32.u64 %0, t; }"
        : "=r"(a) : "l"(p));
    return a;
}
__device__ __forceinline__ void cp_async16(uint32_t dst, const void* src) {
    asm volatile("cp.async.cg.shared.global [%0], [%1], 16;"
                 :: "r"(dst), "l"(src) : "memory");
}
#define CP_COMMIT() asm volatile("cp.async.commit_group;" ::: "memory")
#define CP_WAIT(n)  asm volatile("cp.async.wait_group %0;" :: "n"(n) : "memory")

__device__ __forceinline__ void ldsm_x4(uint32_t* r, uint32_t addr) {
    asm volatile("ldmatrix.sync.aligned.m8n8.x4.shared.b16 {%0,%1,%2,%3}, [%4];"
        : "=r"(r[0]), "=r"(r[1]), "=r"(r[2]), "=r"(r[3]) : "r"(addr));
}
__device__ __forceinline__ void mma16816(float* d, const uint32_t* a,
                                         const uint32_t* b) {
    asm volatile("mma.sync.aligned.m16n8k16.row.col.f32.f16.f16.f32 "
        "{%0,%1,%2,%3}, {%4,%5,%6,%7}, {%8,%9}, {%0,%1,%2,%3};"
        : "+f"(d[0]), "+f"(d[1]), "+f"(d[2]), "+f"(d[3])
        : "r"(a[0]), "r"(a[1]), "r"(a[2]), "r"(a[3]), "r"(b[0]), "r"(b[1]));
}

// ---------------------------------------------------------------------------
// SMEM layout, CTA tile 128x64, BK=32 (R12 skeleton):
//   buf b (b=0,1) at b*16384:
//     A  [128][32]f16 @+0   (8K)
//     Bh [64][32] f16 @+8192  (4K)
//     Bl [64][32] f16 @+12288 (4K)
//   stage (epilogue, union with buffers): float [128][72] = 36864 B @0
//   sBias: 64 floats @36864
// Swizzle: 16B chunk c (0..3) of a 64B row -> c ^ ((row>>1)&3).
// ---------------------------------------------------------------------------
#define BUF_STRIDE 16384
#define SM_BH      8192
#define SM_BL      12288
#define SM_BIAS    36864
#define GEMM_SMEM  37376

template <int OUTMODE>   // 0: leaky -> fp16 plane; 1: fp32 out (+bias2)
__global__ __launch_bounds__(256, 2)
void mma_gemm(const __half* __restrict__ Aq,
              const __half* __restrict__ Bhi, const __half* __restrict__ Blo,
              const float* __restrict__ bias, const float* __restrict__ bias2,
              __half* __restrict__ outQ, float* __restrict__ outF, int N, int K)
{
    extern __shared__ __align__(128) char smem[];
    const uint32_t sbase = smem_u32(smem);
    const int tid  = threadIdx.x;
    const int lane = tid & 31;
    const int w    = tid >> 5;
    const int warpM = w & 3;        // 0..3 -> M rows [warpM*32, +32)
    const int warpN = w >> 2;       // 0..1 -> N cols [warpN*32, +32)
    const int m0 = blockIdx.y * 128;
    const int n0 = blockIdx.x * 64;

    float* sBias = (float*)(smem + SM_BIAS);
    if (tid < 64) {
        float bv = bias[n0 + tid];
        if (bias2) bv += bias2[n0 + tid];
        sBias[tid] = bv;
    }

    float acc[2][4][4];
#pragma unroll
    for (int mt = 0; mt < 2; ++mt)
#pragma unroll
        for (int nt = 0; nt < 4; ++nt)
#pragma unroll
            for (int r = 0; r < 4; ++r) acc[mt][nt][r] = 0.f;

    const int NK = K >> 5;

    // A ldmatrix offsets (proven R12 layout).
    uint32_t offA[2][2], offB[2][2];
#pragma unroll
    for (int mt = 0; mt < 2; ++mt)
#pragma unroll
        for (int s = 0; s < 2; ++s) {
            int row = warpM * 32 + mt * 16 + (lane & 15);
            int ch  = s * 2 + (lane >> 4);
            offA[mt][s] = row * 64 + ((ch ^ ((row >> 1) & 3)) << 4);
        }
    // B ldmatrix offsets (non-trans; [N][K] smem, proven R12 layout).
#pragma unroll
    for (int nh = 0; nh < 2; ++nh)
#pragma unroll
        for (int s = 0; s < 2; ++s) {
            int g   = lane >> 3;
            int row = warpN * 32 + nh * 16 + ((g >> 1) << 3) + (lane & 7);
            int ch  = s * 2 + (g & 1);
            offB[nh][s] = SM_BH + row * 64 + ((ch ^ ((row >> 1) & 3)) << 4);
        }

    auto issue_load = [&](int kt) {
        const uint32_t bb = sbase + (uint32_t)(kt & 1) * BUF_STRIDE;
        const size_t kof = (size_t)kt * 32;
#pragma unroll
        for (int j = 0; j < 2; ++j) {           // A: 512 16B-chunks
            int i = tid + j * 256;
            int row = i >> 2, c = i & 3;
            const __half* src = Aq + (size_t)(m0 + row) * K + kof + c * 8;
            uint32_t dst = bb + row * 64 + ((c ^ ((row >> 1) & 3)) << 4);
            cp_async16(dst, src);
        }
#pragma unroll
        for (int j = 0; j < 2; ++j) {           // B: 512 16B-chunks (hi+lo)
            int i = tid + j * 256;
            int plane = i >> 8, ii = i & 255;
            int row = ii >> 2, c = ii & 3;
            const __half* src =
                (plane ? Blo : Bhi) + (size_t)(n0 + row) * K + kof + c * 8;
            uint32_t dst = bb + SM_BH + plane * 4096 + row * 64 +
                           ((c ^ ((row >> 1) & 3)) << 4);
            cp_async16(dst, src);
        }
        CP_COMMIT();
    };

    issue_load(0);

    for (int kt = 0; kt < NK; ++kt) {
        const uint32_t bb = sbase + (uint32_t)(kt & 1) * BUF_STRIDE;
        if (kt + 1 < NK) { issue_load(kt + 1); CP_WAIT(1); }
        else             { CP_WAIT(0); }
        __syncthreads();

#pragma unroll
        for (int s = 0; s < 2; ++s) {
            uint32_t a[2][4], bh[4][2], bl[4][2];
#pragma unroll
            for (int mt = 0; mt < 2; ++mt)
                ldsm_x4(a[mt], bb + offA[mt][s]);
#pragma unroll
            for (int nh = 0; nh < 2; ++nh) {
                uint32_t t[4];
                ldsm_x4(t, bb + offB[nh][s]);               // hi plane
                bh[nh*2][0]   = t[0]; bh[nh*2][1]   = t[1];
                bh[nh*2+1][0] = t[2]; bh[nh*2+1][1] = t[3];
                ldsm_x4(t, bb + 4096 + offB[nh][s]);        // lo plane
                bl[nh*2][0]   = t[0]; bl[nh*2][1]   = t[1];
                bl[nh*2+1][0] = t[2]; bl[nh*2+1][1] = t[3];
            }
#pragma unroll
            for (int mt = 0; mt < 2; ++mt)
#pragma unroll
                for (int nt = 0; nt < 4; ++nt) {
                    mma16816(acc[mt][nt], a[mt], bh[nt]);
                    mma16816(acc[mt][nt], a[mt], bl[nt]);
                }
        }
        __syncthreads();
    }

    // ---------------- Epilogue: stage fp32 [128][72], fused writeout --------
    float* stage = (float*)smem;
#pragma unroll
    for (int mt = 0; mt < 2; ++mt)
#pragma unroll
        for (int nt = 0; nt < 4; ++nt) {
            int r = warpM * 32 + mt * 16 + (lane >> 2);
            int c = warpN * 32 + nt * 8 + (lane & 3) * 2;
            stage[r * 72 + c]           = acc[mt][nt][0];
            stage[r * 72 + c + 1]       = acc[mt][nt][1];
            stage[(r + 8) * 72 + c]     = acc[mt][nt][2];
            stage[(r + 8) * 72 + c + 1] = acc[mt][nt][3];
        }
    __syncthreads();

    if (OUTMODE == 0) {
#pragma unroll
        for (int j = 0; j < 16; ++j) {
            int i = tid + j * 256;              // 0..4095 (row, col-pair)
            int r = i >> 5, cp = i & 31;
            float v0 = stage[r * 72 + cp * 2]     + sBias[cp * 2];
            float v1 = stage[r * 72 + cp * 2 + 1] + sBias[cp * 2 + 1];
            v0 = (v0 > 0.f) ? v0 : 0.01f * v0;
            v1 = (v1 > 0.f) ? v1 : 0.01f * v1;
            __half2 q = __floats2half2_rn(v0, v1);
            size_t base = ((size_t)(m0 + r) * N + n0) >> 1;
            ((uint32_t*)outQ)[base + cp] = *(uint32_t*)&q;
        }
    } else {
#pragma unroll
        for (int j = 0; j < 32; ++j) {
            int i = tid + j * 256;              // 0..8191
            int r = i >> 6, c = i & 63;
            outF[(size_t)(m0 + r) * N + n0 + c] = stage[r * 72 + c] + sBias[c];
        }
    }
}

// ---------------------------------------------------------------------------
// Weight split fp32 -> fp16 hi + fp16 lo; activation quant fp32 -> fp16
// ---------------------------------------------------------------------------
__global__ void split_w_f16(const float* __restrict__ src,
                            __half* __restrict__ hi, __half* __restrict__ lo,
                            long n4)
{
    long i = (long)blockIdx.x * 256 + threadIdx.x;
    if (i >= n4) return;
    float4 v = ((const float4*)src)[i];
    float vs[4] = {v.x, v.y, v.z, v.w};
    __half h[4], l[4];
#pragma unroll
    for (int k = 0; k < 4; ++k) {
        h[k] = __float2half_rn(vs[k]);
        l[k] = __float2half_rn(vs[k] - __half2float(h[k]));
    }
    *(uint2*)(hi + i * 4) = *(uint2*)h;
    *(uint2*)(lo + i * 4) = *(uint2*)l;
}

__global__ void quant_f16(const float* __restrict__ src,
                          __half* __restrict__ dst, long n4)
{
    long i = (long)blockIdx.x * 256 + threadIdx.x;
    if (i >= n4) return;
    float4 v = ((const float4*)src)[i];
    __half h[4] = { __float2half_rn(v.x), __float2half_rn(v.y),
                    __float2half_rn(v.z), __float2half_rn(v.w) };
    *(uint2*)(dst + i * 4) = *(uint2*)h;
}

// ---------------------------------------------------------------------------
// Scan prep + scan + output GEMV (unchanged from R12)
// ---------------------------------------------------------------------------
__device__ __forceinline__ float2 ffma2(float2 a, float2 b, float2 c) {
    float2 d;
    asm("fma.rn.f32x2 %0, %1, %2, %3;"
        : "=l"(reinterpret_cast<unsigned long long&>(d))
        : "l"(reinterpret_cast<unsigned long long&>(a)),
          "l"(reinterpret_cast<unsigned long long&>(b)),
          "l"(reinterpret_cast<unsigned long long&>(c)));
    return d;
}
__device__ __forceinline__ float fast_sigmoid(float x) {
    return __fdividef(1.f, 1.f + __expf(-x));
}
__device__ __forceinline__ float fast_tanh(float x) {
    return 1.f - __fdividef(2.f, __expf(2.f * x) + 1.f);
}

__global__ void prepack_whh(const float* __restrict__ W)
{
    int i = blockIdx.x * 256 + threadIdx.x;
    if (i >= 40 * GATES) return;
    int p = i / GATES, g = i % GATES;
    const float* wr = W + (size_t)g * HID + p * 4;
    __half2 h01 = __floats2half2_rn(wr[0], wr[1]);
    __half2 h23 = __floats2half2_rn(wr[2], wr[3]);
    uint2 v;
    v.x = *reinterpret_cast<uint32_t*>(&h01);
    v.y = *reinterpret_cast<uint32_t*>(&h23);
    gWt2[(size_t)p * GATES + g] = v;
}

#define SCAN_SMEM (40 * GATES * 8 + 2 * HID * 4 + 2 * GATES * 4)

__global__ __launch_bounds__(GATES, 1)
void lstm_scan(const float* __restrict__ GX, float* __restrict__ Hout)
{
    extern __shared__ unsigned char smem_raw[];
    uint2* sW = reinterpret_cast<uint2*>(smem_raw);
    float* sH = reinterpret_cast<float*>(smem_raw + 40 * GATES * 8);
    float* sG = sH + 2 * HID;

    const int tid  = threadIdx.x;
    const int g    = tid;
    const int row0 = blockIdx.x * 2;

    for (int i = tid; i < 40 * GATES; i += GATES) sW[i] = gWt2[i];
    if (tid < 2 * HID) sH[tid] = 0.f;

    float cc = 0.f;
    const int cr = tid < 2 * HID ? (tid / HID) : 0;
    const int cj = tid < 2 * HID ? (tid - cr * HID) : 0;

    __syncthreads();

    for (int t = 0; t < T_STEPS; ++t) {
        const size_t base = (size_t)t * (BATCH * GATES) + (size_t)row0 * GATES;
        float gx0 = GX[base + g];
        float gx1 = GX[base + GATES + g];

        float2 acc0 = make_float2(0.f, 0.f);
        float2 acc1 = make_float2(0.f, 0.f);
#pragma unroll
        for (int p = 0; p < 40; ++p) {
            uint2 w = sW[p * GATES + g];
            float2 wA = __half22float2(*reinterpret_cast<__half2*>(&w.x));
            float2 wB = __half22float2(*reinterpret_cast<__half2*>(&w.y));
            float4 h0v = *reinterpret_cast<const float4*>(&sH[p * 4]);
            float4 h1v = *reinterpret_cast<const float4*>(&sH[HID + p * 4]);
            acc0 = ffma2(wA, make_float2(h0v.x, h0v.y), acc0);
            acc0 = ffma2(wB, make_float2(h0v.z, h0v.w), acc0);
            acc1 = ffma2(wA, make_float2(h1v.x, h1v.y), acc1);
            acc1 = ffma2(wB, make_float2(h1v.z, h1v.w), acc1);
        }
        float p0 = acc0.x + acc0.y + gx0;
        float p1 = acc1.x + acc1.y + gx1;

        float a0, a1;
        if (g >= 320 && g < 480) { a0 = fast_tanh(p0);    a1 = fast_tanh(p1);    }
        else                     { a0 = fast_sigmoid(p0); a1 = fast_sigmoid(p1); }
        sG[g] = a0;
        sG[GATES + g] = a1;
        __syncthreads();

        if (tid < 2 * HID) {
            const float* Gr = sG + cr * GATES;
            float iv = Gr[cj], fv = Gr[HID + cj], gv = Gr[2 * HID + cj], ov = Gr[3 * HID + cj];
            cc = fv * cc + iv * gv;
            float hv = ov * fast_tanh(cc);
            sH[cr * HID + cj] = hv;
            Hout[(size_t)t * (BATCH * HID) + (size_t)(row0 + cr) * HID + cj] = hv;
        }
        __syncthreads();
    }
}

__global__ __launch_bounds__(256)
void out_gemv(const float* __restrict__ H, const float* __restrict__ W3,
              const float* __restrict__ b3, float* __restrict__ Y)
{
    __shared__ float sW[HID * O_DIM];
    __shared__ float sHr[8 * HID];

    const int tid = threadIdx.x;
    const int r   = tid >> 5;
    const int o   = tid & 31;

    for (int i = tid; i < HID * O_DIM; i += 256) {
        int k = i >> 5, oo = i & 31;
        sW[i] = W3[(size_t)oo * HID + k];
    }
    const size_t mrow0 = (size_t)blockIdx.x * 8;
    for (int i = tid; i < 8 * HID; i += 256)
        sHr[i] = H[mrow0 * HID + i];
    __syncthreads();

    float acc = b3[o];
#pragma unroll 8
    for (int k = 0; k < HID; ++k)
        acc = fmaf(sHr[r * HID + k], sW[k * O_DIM + o], acc);
    Y[(mrow0 + r) * O_DIM + o] = acc;
}

// ---------------------------------------------------------------------------
// Launch
// ---------------------------------------------------------------------------
extern "C" void kernel_launch(void* const* d_in, const int* in_sizes, int n_in,
                              void* d_out, int out_size)
{
    (void)in_sizes; (void)n_in; (void)out_size;
    const float* inputs = (const float*)d_in[0];
    const float* W1     = (const float*)d_in[1];
    const float* b1     = (const float*)d_in[2];
    const float* W2     = (const float*)d_in[3];
    const float* b2     = (const float*)d_in[4];
    const float* W_ih   = (const float*)d_in[5];
    const float* W_hh   = (const float*)d_in[6];
    const float* b_ih   = (const float*)d_in[7];
    const float* b_hh   = (const float*)d_in[8];
    const float* W3     = (const float*)d_in[9];
    const float* b3     = (const float*)d_in[10];
    float* Y = (float*)d_out;

    void *pIq, *pX1q, *pX2q, *pGX, *pH;
    void *pW1h, *pW1l, *pW2h, *pW2l, *pWih, *pWil;
    cudaGetSymbolAddress(&pIq,  gIq);
    cudaGetSymbolAddress(&pX1q, gX1q);
    cudaGetSymbolAddress(&pX2q, gX2q);
    cudaGetSymbolAddress(&pGX,  gGX);   cudaGetSymbolAddress(&pH, gHout);
    cudaGetSymbolAddress(&pW1h, gW1hi); cudaGetSymbolAddress(&pW1l, gW1lo);
    cudaGetSymbolAddress(&pW2h, gW2hi); cudaGetSymbolAddress(&pW2l, gW2lo);
    cudaGetSymbolAddress(&pWih, gWihi); cudaGetSymbolAddress(&pWil, gWilo);

    cudaFuncSetAttribute(mma_gemm<0>, cudaFuncAttributeMaxDynamicSharedMemorySize, GEMM_SMEM);
    cudaFuncSetAttribute(mma_gemm<1>, cudaFuncAttributeMaxDynamicSharedMemorySize, GEMM_SMEM);
    cudaFuncSetAttribute(lstm_scan, cudaFuncAttributeMaxDynamicSharedMemorySize, SCAN_SMEM);

    // Weight splits + scan prepack (once)
    split_w_f16<<<H_DIM * IN_DIM / 4 / 256, 256>>>(W1,
        (__half*)pW1h, (__half*)pW1l, H_DIM * IN_DIM / 4);
    split_w_f16<<<H4 * H_DIM / 4 / 256, 256>>>(W2,
        (__half*)pW2h, (__half*)pW2l, H4 * H_DIM / 4);
    split_w_f16<<<GATES * H4 / 4 / 256, 256>>>(W_ih,
        (__half*)pWih, (__half*)pWil, GATES * H4 / 4);
    prepack_whh<<<(40 * GATES + 255) / 256, 256>>>(W_hh);

    // Chunked batch-parallel pipeline: input quant -> fc1 -> fc2 -> gates
    for (int c = 0; c < MTOT / CHUNK; ++c) {
        const float* Ain = inputs + (size_t)c * CHUNK * IN_DIM;
        quant_f16<<<(long)CHUNK * IN_DIM / 4 / 256, 256>>>(Ain,
            (__half*)pIq, (long)CHUNK * IN_DIM / 4);

        mma_gemm<0><<<dim3(H_DIM / 64, CHUNK / 128), 256, GEMM_SMEM>>>(
            (__half*)pIq, (__half*)pW1h, (__half*)pW1l,
            b1, nullptr, (__half*)pX1q, nullptr, H_DIM, IN_DIM);

        mma_gemm<0><<<dim3(H4 / 64, CHUNK / 128), 256, GEMM_SMEM>>>(
            (__half*)pX1q, (__half*)pW2h, (__half*)pW2l,
            b2, nullptr, (__half*)pX2q, nullptr, H4, H_DIM);

        mma_gemm<1><<<dim3(GATES / 64, CHUNK / 128), 256, GEMM_SMEM>>>(
            (__half*)pX2q, (__half*)pWih, (__half*)pWil,
            b_ih, b_hh, nullptr,
            (float*)pGX + (size_t)c * CHUNK * GATES, GATES, H4);
    }

    // Recurrence + output projection
    lstm_scan<<<BATCH / 2, GATES, SCAN_SMEM>>>((float*)pGX, (float*)pH);
    out_gemv<<<MTOT / 8, 256>>>((float*)pH, W3, b3, Y);
}

// round 15
// speedup vs baseline: 1.2360x; 1.0213x over previous
#include <cuda_runtime.h>
#include <cuda_fp16.h>
#include <cstdint>
#include <cstddef>

// ---------------------------------------------------------------------------
// Problem constants
// ---------------------------------------------------------------------------
#define T_STEPS 2048
#define BATCH   256
#define IN_DIM  64
#define H_DIM   1280
#define H4      320
#define HID     160
#define GATES   640
#define O_DIM   32
#define MTOT    (T_STEPS*BATCH)   // 524288
#define CHUNK   65536             // rows per pipeline chunk (8 chunks)

// ---------------------------------------------------------------------------
// Device scratch (activations/GX fp16; weights fp16 hi+lo)
// ---------------------------------------------------------------------------
__device__ __align__(256) __half gIq [(size_t)CHUNK * IN_DIM];   // 8.4MB
__device__ __align__(256) __half gX1q[(size_t)CHUNK * H_DIM];    // 168MB
__device__ __align__(256) __half gX2q[(size_t)CHUNK * H4];       // 42MB
__device__ __align__(256) __half gGX [(size_t)MTOT * GATES];     // 671MB
__device__ __align__(256) float gHout[(size_t)MTOT * HID];       // 335MB
__device__ __align__(256) __half gW1hi[H_DIM * IN_DIM];
__device__ __align__(256) __half gW1lo[H_DIM * IN_DIM];
__device__ __align__(256) __half gW2hi[H4 * H_DIM];
__device__ __align__(256) __half gW2lo[H4 * H_DIM];
__device__ __align__(256) __half gWihi[GATES * H4];
__device__ __align__(256) __half gWilo[GATES * H4];
__device__ __align__(256) uint2 gWt2[40 * GATES];   // W_hh fp16 pack for scan

// ---------------------------------------------------------------------------
// PTX helpers — base-ISA only (sm_80+ features, legal on .target sm_103)
// ---------------------------------------------------------------------------
__device__ __forceinline__ uint32_t smem_u32(const void* p) {
    uint32_t a;
    asm("{ .reg .u64 t; cvta.to.shared.u64 t, %1; cvt.u32.u64 %0, t; }"
        : "=r"(a) : "l"(p));
    return a;
}
__device__ __forceinline__ void cp_async16(uint32_t dst, const void* src) {
    asm volatile("cp.async.cg.shared.global [%0], [%1], 16;"
                 :: "r"(dst), "l"(src) : "memory");
}
#define CP_COMMIT() asm volatile("cp.async.commit_group;" ::: "memory")
#define CP_WAIT(n)  asm volatile("cp.async.wait_group %0;" :: "n"(n) : "memory")

__device__ __forceinline__ void ldsm_x4(uint32_t* r, uint32_t addr) {
    asm volatile("ldmatrix.sync.aligned.m8n8.x4.shared.b16 {%0,%1,%2,%3}, [%4];"
        : "=r"(r[0]), "=r"(r[1]), "=r"(r[2]), "=r"(r[3]) : "r"(addr));
}
__device__ __forceinline__ void mma16816(float* d, const uint32_t* a,
                                         const uint32_t* b) {
    asm volatile("mma.sync.aligned.m16n8k16.row.col.f32.f16.f16.f32 "
        "{%0,%1,%2,%3}, {%4,%5,%6,%7}, {%8,%9}, {%0,%1,%2,%3};"
        : "+f"(d[0]), "+f"(d[1]), "+f"(d[2]), "+f"(d[3])
        : "r"(a[0]), "r"(a[1]), "r"(a[2]), "r"(a[3]), "r"(b[0]), "r"(b[1]));
}

// ---------------------------------------------------------------------------
// SMEM layout, CTA tile 256x64, BK=32, 8 warps (4M x 2N), warp tile 64x32:
//   buf b (b=0,1) at b*24576:
//     A  [256][32]f16 @+0     (16K)
//     Bh [ 64][32]f16 @+16384 (4K)
//     Bl [ 64][32]f16 @+20480 (4K)
// Swizzle: 16B chunk c (0..3) of a 64B row -> c ^ ((row>>1)&3).
// 16-row steps preserve the swizzle phase.
// ---------------------------------------------------------------------------
#define BUF_STRIDE 24576
#define SM_BH      16384
#define GEMM_SMEM  49152

template <int ACT>   // 1: leaky_relu; 0: plain (+bias2)  — both write fp16
__global__ __launch_bounds__(256, 2)
void mma_gemm(const __half* __restrict__ Aq,
              const __half* __restrict__ Bhi, const __half* __restrict__ Blo,
              const float* __restrict__ bias, const float* __restrict__ bias2,
              __half* __restrict__ outQ, int N, int K)
{
    extern __shared__ __align__(128) char smem[];
    const uint32_t sbase = smem_u32(smem);
    const int tid  = threadIdx.x;
    const int lane = tid & 31;
    const int w    = tid >> 5;
    const int warpM = w & 3;        // 0..3 -> M rows [warpM*64, +64)
    const int warpN = w >> 2;       // 0..1 -> N cols [warpN*32, +32)
    const int m0 = blockIdx.y * 256;
    const int n0 = blockIdx.x * 64;

    float acc[4][4][4];
#pragma unroll
    for (int mt = 0; mt < 4; ++mt)
#pragma unroll
        for (int nt = 0; nt < 4; ++nt)
#pragma unroll
            for (int r = 0; r < 4; ++r) acc[mt][nt][r] = 0.f;

    const int NK = K >> 5;

    // A ldmatrix offsets: row = warpM*64 + mt*16 + (lane&15), k-octet s*2+(lane>>4)
    uint32_t offA[4][2], offB[2][2];
#pragma unroll
    for (int mt = 0; mt < 4; ++mt)
#pragma unroll
        for (int s = 0; s < 2; ++s) {
            int row = warpM * 64 + mt * 16 + (lane & 15);
            int ch  = s * 2 + (lane >> 4);
            offA[mt][s] = row * 64 + ((ch ^ ((row >> 1) & 3)) << 4);
        }
    // B ldmatrix offsets (non-trans; [N][K] smem): proven R12/R14 layout.
#pragma unroll
    for (int nh = 0; nh < 2; ++nh)
#pragma unroll
        for (int s = 0; s < 2; ++s) {
            int g   = lane >> 3;
            int row = warpN * 32 + nh * 16 + ((g >> 1) << 3) + (lane & 7);
            int ch  = s * 2 + (g & 1);
            offB[nh][s] = SM_BH + row * 64 + ((ch ^ ((row >> 1) & 3)) << 4);
        }

    auto issue_load = [&](int kt) {
        const uint32_t bb = sbase + (uint32_t)(kt & 1) * BUF_STRIDE;
        const size_t kof = (size_t)kt * 32;
#pragma unroll
        for (int j = 0; j < 4; ++j) {           // A: 1024 16B-chunks
            int i = tid + j * 256;
            int row = i >> 2, c = i & 3;
            const __half* src = Aq + (size_t)(m0 + row) * K + kof + c * 8;
            uint32_t dst = bb + row * 64 + ((c ^ ((row >> 1) & 3)) << 4);
            cp_async16(dst, src);
        }
#pragma unroll
        for (int j = 0; j < 2; ++j) {           // B: 512 16B-chunks (hi+lo)
            int i = tid + j * 256;
            int plane = i >> 8, ii = i & 255;
            int row = ii >> 2, c = ii & 3;
            const __half* src =
                (plane ? Blo : Bhi) + (size_t)(n0 + row) * K + kof + c * 8;
            uint32_t dst = bb + SM_BH + plane * 4096 + row * 64 +
                           ((c ^ ((row >> 1) & 3)) << 4);
            cp_async16(dst, src);
        }
        CP_COMMIT();
    };

    issue_load(0);

    for (int kt = 0; kt < NK; ++kt) {
        const uint32_t bb = sbase + (uint32_t)(kt & 1) * BUF_STRIDE;
        if (kt + 1 < NK) { issue_load(kt + 1); CP_WAIT(1); }
        else             { CP_WAIT(0); }
        __syncthreads();

#pragma unroll
        for (int s = 0; s < 2; ++s) {
            uint32_t a[4][4], bh[4][2], bl[4][2];
#pragma unroll
            for (int mt = 0; mt < 4; ++mt)
                ldsm_x4(a[mt], bb + offA[mt][s]);
#pragma unroll
            for (int nh = 0; nh < 2; ++nh) {
                uint32_t t[4];
                ldsm_x4(t, bb + offB[nh][s]);               // hi plane
                bh[nh*2][0]   = t[0]; bh[nh*2][1]   = t[1];
                bh[nh*2+1][0] = t[2]; bh[nh*2+1][1] = t[3];
                ldsm_x4(t, bb + 4096 + offB[nh][s]);        // lo plane
                bl[nh*2][0]   = t[0]; bl[nh*2][1]   = t[1];
                bl[nh*2+1][0] = t[2]; bl[nh*2+1][1] = t[3];
            }
#pragma unroll
            for (int mt = 0; mt < 4; ++mt)
#pragma unroll
                for (int nt = 0; nt < 4; ++nt) {
                    mma16816(acc[mt][nt], a[mt], bh[nt]);
                    mma16816(acc[mt][nt], a[mt], bl[nt]);
                }
        }
        __syncthreads();
    }

    // ---------------- Epilogue: direct half2 stores from fragments ---------
    // c-frag: (r, c),(r, c+1),(r+8, c),(r+8, c+1); r=warpM*64+mt*16+(lane>>2),
    // c = warpN*32 + nt*8 + (lane&3)*2.
    const int cbase = n0 + warpN * 32 + (lane & 3) * 2;
    float bv0[4], bv1[4];
#pragma unroll
    for (int nt = 0; nt < 4; ++nt) {
        int c = cbase + nt * 8;
        bv0[nt] = bias[c]     + (bias2 ? bias2[c]     : 0.f);
        bv1[nt] = bias[c + 1] + (bias2 ? bias2[c + 1] : 0.f);
    }
#pragma unroll
    for (int mt = 0; mt < 4; ++mt) {
        int r = m0 + warpM * 64 + mt * 16 + (lane >> 2);
#pragma unroll
        for (int nt = 0; nt < 4; ++nt) {
            int c = cbase + nt * 8;
            float v0 = acc[mt][nt][0] + bv0[nt];
            float v1 = acc[mt][nt][1] + bv1[nt];
            float v2 = acc[mt][nt][2] + bv0[nt];
            float v3 = acc[mt][nt][3] + bv1[nt];
            if (ACT) {
                v0 = (v0 > 0.f) ? v0 : 0.01f * v0;
                v1 = (v1 > 0.f) ? v1 : 0.01f * v1;
                v2 = (v2 > 0.f) ? v2 : 0.01f * v2;
                v3 = (v3 > 0.f) ? v3 : 0.01f * v3;
            }
            __half2 q0 = __floats2half2_rn(v0, v1);
            __half2 q1 = __floats2half2_rn(v2, v3);
            *(uint32_t*)(outQ + (size_t)r * N + c)       = *(uint32_t*)&q0;
            *(uint32_t*)(outQ + (size_t)(r + 8) * N + c) = *(uint32_t*)&q1;
        }
    }
}

// ---------------------------------------------------------------------------
// Weight split fp32 -> fp16 hi + fp16 lo; activation quant fp32 -> fp16
// ---------------------------------------------------------------------------
__global__ void split_w_f16(const float* __restrict__ src,
                            __half* __restrict__ hi, __half* __restrict__ lo,
                            long n4)
{
    long i = (long)blockIdx.x * 256 + threadIdx.x;
    if (i >= n4) return;
    float4 v = ((const float4*)src)[i];
    float vs[4] = {v.x, v.y, v.z, v.w};
    __half h[4], l[4];
#pragma unroll
    for (int k = 0; k < 4; ++k) {
        h[k] = __float2half_rn(vs[k]);
        l[k] = __float2half_rn(vs[k] - __half2float(h[k]));
    }
    *(uint2*)(hi + i * 4) = *(uint2*)h;
    *(uint2*)(lo + i * 4) = *(uint2*)l;
}

__global__ void quant_f16(const float* __restrict__ src,
                          __half* __restrict__ dst, long n4)
{
    long i = (long)blockIdx.x * 256 + threadIdx.x;
    if (i >= n4) return;
    float4 v = ((const float4*)src)[i];
    __half h[4] = { __float2half_rn(v.x), __float2half_rn(v.y),
                    __float2half_rn(v.z), __float2half_rn(v.w) };
    *(uint2*)(dst + i * 4) = *(uint2*)h;
}

// ---------------------------------------------------------------------------
// Scan prep + scan + output GEMV (GX now fp16)
// ---------------------------------------------------------------------------
__device__ __forceinline__ float2 ffma2(float2 a, float2 b, float2 c) {
    float2 d;
    asm("fma.rn.f32x2 %0, %1, %2, %3;"
        : "=l"(reinterpret_cast<unsigned long long&>(d))
        : "l"(reinterpret_cast<unsigned long long&>(a)),
          "l"(reinterpret_cast<unsigned long long&>(b)),
          "l"(reinterpret_cast<unsigned long long&>(c)));
    return d;
}
__device__ __forceinline__ float fast_sigmoid(float x) {
    return __fdividef(1.f, 1.f + __expf(-x));
}
__device__ __forceinline__ float fast_tanh(float x) {
    return 1.f - __fdividef(2.f, __expf(2.f * x) + 1.f);
}

__global__ void prepack_whh(const float* __restrict__ W)
{
    int i = blockIdx.x * 256 + threadIdx.x;
    if (i >= 40 * GATES) return;
    int p = i / GATES, g = i % GATES;
    const float* wr = W + (size_t)g * HID + p * 4;
    __half2 h01 = __floats2half2_rn(wr[0], wr[1]);
    __half2 h23 = __floats2half2_rn(wr[2], wr[3]);
    uint2 v;
    v.x = *reinterpret_cast<uint32_t*>(&h01);
    v.y = *reinterpret_cast<uint32_t*>(&h23);
    gWt2[(size_t)p * GATES + g] = v;
}

#define SCAN_SMEM (40 * GATES * 8 + 2 * HID * 4 + 2 * GATES * 4)

__global__ __launch_bounds__(GATES, 1)
void lstm_scan(const __half* __restrict__ GX, float* __restrict__ Hout)
{
    extern __shared__ unsigned char smem_raw[];
    uint2* sW = reinterpret_cast<uint2*>(smem_raw);
    float* sH = reinterpret_cast<float*>(smem_raw + 40 * GATES * 8);
    float* sG = sH + 2 * HID;

    const int tid  = threadIdx.x;
    const int g    = tid;
    const int row0 = blockIdx.x * 2;

    for (int i = tid; i < 40 * GATES; i += GATES) sW[i] = gWt2[i];
    if (tid < 2 * HID) sH[tid] = 0.f;

    float cc = 0.f;
    const int cr = tid < 2 * HID ? (tid / HID) : 0;
    const int cj = tid < 2 * HID ? (tid - cr * HID) : 0;

    __syncthreads();

    for (int t = 0; t < T_STEPS; ++t) {
        const size_t base = (size_t)t * (BATCH * GATES) + (size_t)row0 * GATES;
        float gx0 = __half2float(GX[base + g]);
        float gx1 = __half2float(GX[base + GATES + g]);

        float2 acc0 = make_float2(0.f, 0.f);
        float2 acc1 = make_float2(0.f, 0.f);
#pragma unroll
        for (int p = 0; p < 40; ++p) {
            uint2 w = sW[p * GATES + g];
            float2 wA = __half22float2(*reinterpret_cast<__half2*>(&w.x));
            float2 wB = __half22float2(*reinterpret_cast<__half2*>(&w.y));
            float4 h0v = *reinterpret_cast<const float4*>(&sH[p * 4]);
            float4 h1v = *reinterpret_cast<const float4*>(&sH[HID + p * 4]);
            acc0 = ffma2(wA, make_float2(h0v.x, h0v.y), acc0);
            acc0 = ffma2(wB, make_float2(h0v.z, h0v.w), acc0);
            acc1 = ffma2(wA, make_float2(h1v.x, h1v.y), acc1);
            acc1 = ffma2(wB, make_float2(h1v.z, h1v.w), acc1);
        }
        float p0 = acc0.x + acc0.y + gx0;
        float p1 = acc1.x + acc1.y + gx1;

        float a0, a1;
        if (g >= 320 && g < 480) { a0 = fast_tanh(p0);    a1 = fast_tanh(p1);    }
        else                     { a0 = fast_sigmoid(p0); a1 = fast_sigmoid(p1); }
        sG[g] = a0;
        sG[GATES + g] = a1;
        __syncthreads();

        if (tid < 2 * HID) {
            const float* Gr = sG + cr * GATES;
            float iv = Gr[cj], fv = Gr[HID + cj], gv = Gr[2 * HID + cj], ov = Gr[3 * HID + cj];
            cc = fv * cc + iv * gv;
            float hv = ov * fast_tanh(cc);
            sH[cr * HID + cj] = hv;
            Hout[(size_t)t * (BATCH * HID) + (size_t)(row0 + cr) * HID + cj] = hv;
        }
        __syncthreads();
    }
}

__global__ __launch_bounds__(256)
void out_gemv(const float* __restrict__ H, const float* __restrict__ W3,
              const float* __restrict__ b3, float* __restrict__ Y)
{
    __shared__ float sW[HID * O_DIM];
    __shared__ float sHr[8 * HID];

    const int tid = threadIdx.x;
    const int r   = tid >> 5;
    const int o   = tid & 31;

    for (int i = tid; i < HID * O_DIM; i += 256) {
        int k = i >> 5, oo = i & 31;
        sW[i] = W3[(size_t)oo * HID + k];
    }
    const size_t mrow0 = (size_t)blockIdx.x * 8;
    for (int i = tid; i < 8 * HID; i += 256)
        sHr[i] = H[mrow0 * HID + i];
    __syncthreads();

    float acc = b3[o];
#pragma unroll 8
    for (int k = 0; k < HID; ++k)
        acc = fmaf(sHr[r * HID + k], sW[k * O_DIM + o], acc);
    Y[(mrow0 + r) * O_DIM + o] = acc;
}

// ---------------------------------------------------------------------------
// Launch
// ---------------------------------------------------------------------------
extern "C" void kernel_launch(void* const* d_in, const int* in_sizes, int n_in,
                              void* d_out, int out_size)
{
    (void)in_sizes; (void)n_in; (void)out_size;
    const float* inputs = (const float*)d_in[0];
    const float* W1     = (const float*)d_in[1];
    const float* b1     = (const float*)d_in[2];
    const float* W2     = (const float*)d_in[3];
    const float* b2     = (const float*)d_in[4];
    const float* W_ih   = (const float*)d_in[5];
    const float* W_hh   = (const float*)d_in[6];
    const float* b_ih   = (const float*)d_in[7];
    const float* b_hh   = (const float*)d_in[8];
    const float* W3     = (const float*)d_in[9];
    const float* b3     = (const float*)d_in[10];
    float* Y = (float*)d_out;

    void *pIq, *pX1q, *pX2q, *pGX, *pH;
    void *pW1h, *pW1l, *pW2h, *pW2l, *pWih, *pWil;
    cudaGetSymbolAddress(&pIq,  gIq);
    cudaGetSymbolAddress(&pX1q, gX1q);
    cudaGetSymbolAddress(&pX2q, gX2q);
    cudaGetSymbolAddress(&pGX,  gGX);   cudaGetSymbolAddress(&pH, gHout);
    cudaGetSymbolAddress(&pW1h, gW1hi); cudaGetSymbolAddress(&pW1l, gW1lo);
    cudaGetSymbolAddress(&pW2h, gW2hi); cudaGetSymbolAddress(&pW2l, gW2lo);
    cudaGetSymbolAddress(&pWih, gWihi); cudaGetSymbolAddress(&pWil, gWilo);

    cudaFuncSetAttribute(mma_gemm<0>, cudaFuncAttributeMaxDynamicSharedMemorySize, GEMM_SMEM);
    cudaFuncSetAttribute(mma_gemm<1>, cudaFuncAttributeMaxDynamicSharedMemorySize, GEMM_SMEM);
    cudaFuncSetAttribute(lstm_scan, cudaFuncAttributeMaxDynamicSharedMemorySize, SCAN_SMEM);

    // Weight splits + scan prepack (once)
    split_w_f16<<<H_DIM * IN_DIM / 4 / 256, 256>>>(W1,
        (__half*)pW1h, (__half*)pW1l, H_DIM * IN_DIM / 4);
    split_w_f16<<<H4 * H_DIM / 4 / 256, 256>>>(W2,
        (__half*)pW2h, (__half*)pW2l, H4 * H_DIM / 4);
    split_w_f16<<<GATES * H4 / 4 / 256, 256>>>(W_ih,
        (__half*)pWih, (__half*)pWil, GATES * H4 / 4);
    prepack_whh<<<(40 * GATES + 255) / 256, 256>>>(W_hh);

    // Chunked batch-parallel pipeline: input quant -> fc1 -> fc2 -> gates
    for (int c = 0; c < MTOT / CHUNK; ++c) {
        const float* Ain = inputs + (size_t)c * CHUNK * IN_DIM;
        quant_f16<<<(long)CHUNK * IN_DIM / 4 / 256, 256>>>(Ain,
            (__half*)pIq, (long)CHUNK * IN_DIM / 4);

        mma_gemm<1><<<dim3(H_DIM / 64, CHUNK / 256), 256, GEMM_SMEM>>>(
            (__half*)pIq, (__half*)pW1h, (__half*)pW1l,
            b1, nullptr, (__half*)pX1q, H_DIM, IN_DIM);

        mma_gemm<1><<<dim3(H4 / 64, CHUNK / 256), 256, GEMM_SMEM>>>(
            (__half*)pX1q, (__half*)pW2h, (__half*)pW2l,
            b2, nullptr, (__half*)pX2q, H4, H_DIM);

        mma_gemm<0><<<dim3(GATES / 64, CHUNK / 256), 256, GEMM_SMEM>>>(
            (__half*)pX2q, (__half*)pWih, (__half*)pWil,
            b_ih, b_hh, (__half*)pGX + (size_t)c * CHUNK * GATES,
            GATES, H4);
    }

    // Recurrence + output projection
    lstm_scan<<<BATCH / 2, GATES, SCAN_SMEM>>>((__half*)pGX, (float*)pH);
    out_gemv<<<MTOT / 8, 256>>>((float*)pH, W3, b3, Y);
}

// round 16
// speedup vs baseline: 1.3935x; 1.1275x over previous
#include <cuda_runtime.h>
#include <cuda_fp16.h>
#include <cstdint>
#include <cstddef>

// ---------------------------------------------------------------------------
// Problem constants
// ---------------------------------------------------------------------------
#define T_STEPS 2048
#define BATCH   256
#define IN_DIM  64
#define H_DIM   1280
#define H4      320
#define HID     160
#define GATES   640
#define O_DIM   32
#define MTOT    (T_STEPS*BATCH)   // 524288
#define CHUNK   65536             // rows per pipeline chunk (8 chunks)

// ---------------------------------------------------------------------------
// Device scratch (activations/GX/weights all fp16)
// ---------------------------------------------------------------------------
__device__ __align__(256) __half gIq [(size_t)CHUNK * IN_DIM];   // 8.4MB
__device__ __align__(256) __half gX1q[(size_t)CHUNK * H_DIM];    // 168MB
__device__ __align__(256) __half gX2q[(size_t)CHUNK * H4];       // 42MB
__device__ __align__(256) __half gGX [(size_t)MTOT * GATES];     // 671MB
__device__ __align__(256) float gHout[(size_t)MTOT * HID];       // 335MB
__device__ __align__(256) __half gW1q[H_DIM * IN_DIM];
__device__ __align__(256) __half gW2q[H4 * H_DIM];
__device__ __align__(256) __half gWiq[GATES * H4];
__device__ __align__(256) uint2 gWt2[40 * GATES];   // W_hh fp16 pack for scan

// ---------------------------------------------------------------------------
// PTX helpers — base-ISA only (sm_80+ features, legal on .target sm_103)
// ---------------------------------------------------------------------------
__device__ __forceinline__ uint32_t smem_u32(const void* p) {
    uint32_t a;
    asm("{ .reg .u64 t; cvta.to.shared.u64 t, %1; cvt.u32.u64 %0, t; }"
        : "=r"(a) : "l"(p));
    return a;
}
__device__ __forceinline__ void cp_async16(uint32_t dst, const void* src) {
    asm volatile("cp.async.cg.shared.global [%0], [%1], 16;"
                 :: "r"(dst), "l"(src) : "memory");
}
#define CP_COMMIT() asm volatile("cp.async.commit_group;" ::: "memory")
#define CP_WAIT(n)  asm volatile("cp.async.wait_group %0;" :: "n"(n) : "memory")

__device__ __forceinline__ void ldsm_x4(uint32_t* r, uint32_t addr) {
    asm volatile("ldmatrix.sync.aligned.m8n8.x4.shared.b16 {%0,%1,%2,%3}, [%4];"
        : "=r"(r[0]), "=r"(r[1]), "=r"(r[2]), "=r"(r[3]) : "r"(addr));
}
__device__ __forceinline__ void mma16816(float* d, const uint32_t* a,
                                         const uint32_t* b) {
    asm volatile("mma.sync.aligned.m16n8k16.row.col.f32.f16.f16.f32 "
        "{%0,%1,%2,%3}, {%4,%5,%6,%7}, {%8,%9}, {%0,%1,%2,%3};"
        : "+f"(d[0]), "+f"(d[1]), "+f"(d[2]), "+f"(d[3])
        : "r"(a[0]), "r"(a[1]), "r"(a[2]), "r"(a[3]), "r"(b[0]), "r"(b[1]));
}

// ---------------------------------------------------------------------------
// SMEM layout, CTA tile 256x64, BK=32, 8 warps (4M x 2N), warp tile 64x32:
//   buf b (b=0,1) at b*20480:
//     A [256][32]f16 @+0     (16K)
//     B [ 64][32]f16 @+16384 (4K)
// Swizzle: 16B chunk c (0..3) of a 64B row -> c ^ ((row>>1)&3).
// ---------------------------------------------------------------------------
#define BUF_STRIDE 20480
#define SM_B       16384
#define GEMM_SMEM  40960

template <int ACT>   // 1: leaky_relu; 0: plain (+bias2)  — both write fp16
__global__ __launch_bounds__(256, 2)
void mma_gemm(const __half* __restrict__ Aq, const __half* __restrict__ Bq,
              const float* __restrict__ bias, const float* __restrict__ bias2,
              __half* __restrict__ outQ, int N, int K)
{
    extern __shared__ __align__(128) char smem[];
    const uint32_t sbase = smem_u32(smem);
    const int tid  = threadIdx.x;
    const int lane = tid & 31;
    const int w    = tid >> 5;
    const int warpM = w & 3;        // 0..3 -> M rows [warpM*64, +64)
    const int warpN = w >> 2;       // 0..1 -> N cols [warpN*32, +32)
    const int m0 = blockIdx.y * 256;
    const int n0 = blockIdx.x * 64;

    float acc[4][4][4];
#pragma unroll
    for (int mt = 0; mt < 4; ++mt)
#pragma unroll
        for (int nt = 0; nt < 4; ++nt)
#pragma unroll
            for (int r = 0; r < 4; ++r) acc[mt][nt][r] = 0.f;

    const int NK = K >> 5;

    // A ldmatrix offsets (proven layout)
    uint32_t offA[4][2], offB[2][2];
#pragma unroll
    for (int mt = 0; mt < 4; ++mt)
#pragma unroll
        for (int s = 0; s < 2; ++s) {
            int row = warpM * 64 + mt * 16 + (lane & 15);
            int ch  = s * 2 + (lane >> 4);
            offA[mt][s] = row * 64 + ((ch ^ ((row >> 1) & 3)) << 4);
        }
    // B ldmatrix offsets (non-trans; [N][K] smem; proven layout)
#pragma unroll
    for (int nh = 0; nh < 2; ++nh)
#pragma unroll
        for (int s = 0; s < 2; ++s) {
            int g   = lane >> 3;
            int row = warpN * 32 + nh * 16 + ((g >> 1) << 3) + (lane & 7);
            int ch  = s * 2 + (g & 1);
            offB[nh][s] = SM_B + row * 64 + ((ch ^ ((row >> 1) & 3)) << 4);
        }

    auto issue_load = [&](int kt) {
        const uint32_t bb = sbase + (uint32_t)(kt & 1) * BUF_STRIDE;
        const size_t kof = (size_t)kt * 32;
#pragma unroll
        for (int j = 0; j < 4; ++j) {           // A: 1024 16B-chunks
            int i = tid + j * 256;
            int row = i >> 2, c = i & 3;
            const __half* src = Aq + (size_t)(m0 + row) * K + kof + c * 8;
            uint32_t dst = bb + row * 64 + ((c ^ ((row >> 1) & 3)) << 4);
            cp_async16(dst, src);
        }
        {                                        // B: 256 16B-chunks
            int row = tid >> 2, c = tid & 3;
            const __half* src = Bq + (size_t)(n0 + row) * K + kof + c * 8;
            uint32_t dst = bb + SM_B + row * 64 + ((c ^ ((row >> 1) & 3)) << 4);
            cp_async16(dst, src);
        }
        CP_COMMIT();
    };

    issue_load(0);

    for (int kt = 0; kt < NK; ++kt) {
        const uint32_t bb = sbase + (uint32_t)(kt & 1) * BUF_STRIDE;
        if (kt + 1 < NK) { issue_load(kt + 1); CP_WAIT(1); }
        else             { CP_WAIT(0); }
        __syncthreads();

#pragma unroll
        for (int s = 0; s < 2; ++s) {
            uint32_t a[4][4], bh[4][2];
#pragma unroll
            for (int mt = 0; mt < 4; ++mt)
                ldsm_x4(a[mt], bb + offA[mt][s]);
#pragma unroll
            for (int nh = 0; nh < 2; ++nh) {
                uint32_t t[4];
                ldsm_x4(t, bb + offB[nh][s]);
                bh[nh*2][0]   = t[0]; bh[nh*2][1]   = t[1];
                bh[nh*2+1][0] = t[2]; bh[nh*2+1][1] = t[3];
            }
#pragma unroll
            for (int mt = 0; mt < 4; ++mt)
#pragma unroll
                for (int nt = 0; nt < 4; ++nt)
                    mma16816(acc[mt][nt], a[mt], bh[nt]);
        }
        __syncthreads();
    }

    // ---------------- Epilogue: direct half2 stores from fragments ---------
    const int cbase = n0 + warpN * 32 + (lane & 3) * 2;
    float bv0[4], bv1[4];
#pragma unroll
    for (int nt = 0; nt < 4; ++nt) {
        int c = cbase + nt * 8;
        bv0[nt] = bias[c]     + (bias2 ? bias2[c]     : 0.f);
        bv1[nt] = bias[c + 1] + (bias2 ? bias2[c + 1] : 0.f);
    }
#pragma unroll
    for (int mt = 0; mt < 4; ++mt) {
        int r = m0 + warpM * 64 + mt * 16 + (lane >> 2);
#pragma unroll
        for (int nt = 0; nt < 4; ++nt) {
            int c = cbase + nt * 8;
            float v0 = acc[mt][nt][0] + bv0[nt];
            float v1 = acc[mt][nt][1] + bv1[nt];
            float v2 = acc[mt][nt][2] + bv0[nt];
            float v3 = acc[mt][nt][3] + bv1[nt];
            if (ACT) {
                v0 = (v0 > 0.f) ? v0 : 0.01f * v0;
                v1 = (v1 > 0.f) ? v1 : 0.01f * v1;
                v2 = (v2 > 0.f) ? v2 : 0.01f * v2;
                v3 = (v3 > 0.f) ? v3 : 0.01f * v3;
            }
            __half2 q0 = __floats2half2_rn(v0, v1);
            __half2 q1 = __floats2half2_rn(v2, v3);
            *(uint32_t*)(outQ + (size_t)r * N + c)       = *(uint32_t*)&q0;
            *(uint32_t*)(outQ + (size_t)(r + 8) * N + c) = *(uint32_t*)&q1;
        }
    }
}

// ---------------------------------------------------------------------------
// fp32 -> fp16 quant (weights and activations)
// ---------------------------------------------------------------------------
__global__ void quant_f16(const float* __restrict__ src,
                          __half* __restrict__ dst, long n4)
{
    long i = (long)blockIdx.x * 256 + threadIdx.x;
    if (i >= n4) return;
    float4 v = ((const float4*)src)[i];
    __half h[4] = { __float2half_rn(v.x), __float2half_rn(v.y),
                    __float2half_rn(v.z), __float2half_rn(v.w) };
    *(uint2*)(dst + i * 4) = *(uint2*)h;
}

// ---------------------------------------------------------------------------
// Scan prep + scan + output GEMV (GX fp16)
// ---------------------------------------------------------------------------
__device__ __forceinline__ float2 ffma2(float2 a, float2 b, float2 c) {
    float2 d;
    asm("fma.rn.f32x2 %0, %1, %2, %3;"
        : "=l"(reinterpret_cast<unsigned long long&>(d))
        : "l"(reinterpret_cast<unsigned long long&>(a)),
          "l"(reinterpret_cast<unsigned long long&>(b)),
          "l"(reinterpret_cast<unsigned long long&>(c)));
    return d;
}
__device__ __forceinline__ float fast_sigmoid(float x) {
    return __fdividef(1.f, 1.f + __expf(-x));
}
__device__ __forceinline__ float fast_tanh(float x) {
    return 1.f - __fdividef(2.f, __expf(2.f * x) + 1.f);
}

__global__ void prepack_whh(const float* __restrict__ W)
{
    int i = blockIdx.x * 256 + threadIdx.x;
    if (i >= 40 * GATES) return;
    int p = i / GATES, g = i % GATES;
    const float* wr = W + (size_t)g * HID + p * 4;
    __half2 h01 = __floats2half2_rn(wr[0], wr[1]);
    __half2 h23 = __floats2half2_rn(wr[2], wr[3]);
    uint2 v;
    v.x = *reinterpret_cast<uint32_t*>(&h01);
    v.y = *reinterpret_cast<uint32_t*>(&h23);
    gWt2[(size_t)p * GATES + g] = v;
}

#define SCAN_SMEM (40 * GATES * 8 + 2 * HID * 4 + 2 * GATES * 4)

__global__ __launch_bounds__(GATES, 1)
void lstm_scan(const __half* __restrict__ GX, float* __restrict__ Hout)
{
    extern __shared__ unsigned char smem_raw[];
    uint2* sW = reinterpret_cast<uint2*>(smem_raw);
    float* sH = reinterpret_cast<float*>(smem_raw + 40 * GATES * 8);
    float* sG = sH + 2 * HID;

    const int tid  = threadIdx.x;
    const int g    = tid;
    const int row0 = blockIdx.x * 2;

    for (int i = tid; i < 40 * GATES; i += GATES) sW[i] = gWt2[i];
    if (tid < 2 * HID) sH[tid] = 0.f;

    float cc = 0.f;
    const int cr = tid < 2 * HID ? (tid / HID) : 0;
    const int cj = tid < 2 * HID ? (tid - cr * HID) : 0;

    __syncthreads();

    for (int t = 0; t < T_STEPS; ++t) {
        const size_t base = (size_t)t * (BATCH * GATES) + (size_t)row0 * GATES;
        float gx0 = __half2float(GX[base + g]);
        float gx1 = __half2float(GX[base + GATES + g]);

        float2 acc0 = make_float2(0.f, 0.f);
        float2 acc1 = make_float2(0.f, 0.f);
#pragma unroll
        for (int p = 0; p < 40; ++p) {
            uint2 w = sW[p * GATES + g];
            float2 wA = __half22float2(*reinterpret_cast<__half2*>(&w.x));
            float2 wB = __half22float2(*reinterpret_cast<__half2*>(&w.y));
            float4 h0v = *reinterpret_cast<const float4*>(&sH[p * 4]);
            float4 h1v = *reinterpret_cast<const float4*>(&sH[HID + p * 4]);
            acc0 = ffma2(wA, make_float2(h0v.x, h0v.y), acc0);
            acc0 = ffma2(wB, make_float2(h0v.z, h0v.w), acc0);
            acc1 = ffma2(wA, make_float2(h1v.x, h1v.y), acc1);
            acc1 = ffma2(wB, make_float2(h1v.z, h1v.w), acc1);
        }
        float p0 = acc0.x + acc0.y + gx0;
        float p1 = acc1.x + acc1.y + gx1;

        float a0, a1;
        if (g >= 320 && g < 480) { a0 = fast_tanh(p0);    a1 = fast_tanh(p1);    }
        else                     { a0 = fast_sigmoid(p0); a1 = fast_sigmoid(p1); }
        sG[g] = a0;
        sG[GATES + g] = a1;
        __syncthreads();

        if (tid < 2 * HID) {
            const float* Gr = sG + cr * GATES;
            float iv = Gr[cj], fv = Gr[HID + cj], gv = Gr[2 * HID + cj], ov = Gr[3 * HID + cj];
            cc = fv * cc + iv * gv;
            float hv = ov * fast_tanh(cc);
            sH[cr * HID + cj] = hv;
            Hout[(size_t)t * (BATCH * HID) + (size_t)(row0 + cr) * HID + cj] = hv;
        }
        __syncthreads();
    }
}

__global__ __launch_bounds__(256)
void out_gemv(const float* __restrict__ H, const float* __restrict__ W3,
              const float* __restrict__ b3, float* __restrict__ Y)
{
    __shared__ float sW[HID * O_DIM];
    __shared__ float sHr[8 * HID];

    const int tid = threadIdx.x;
    const int r   = tid >> 5;
    const int o   = tid & 31;

    for (int i = tid; i < HID * O_DIM; i += 256) {
        int k = i >> 5, oo = i & 31;
        sW[i] = W3[(size_t)oo * HID + k];
    }
    const size_t mrow0 = (size_t)blockIdx.x * 8;
    for (int i = tid; i < 8 * HID; i += 256)
        sHr[i] = H[mrow0 * HID + i];
    __syncthreads();

    float acc = b3[o];
#pragma unroll 8
    for (int k = 0; k < HID; ++k)
        acc = fmaf(sHr[r * HID + k], sW[k * O_DIM + o], acc);
    Y[(mrow0 + r) * O_DIM + o] = acc;
}

// ---------------------------------------------------------------------------
// Launch
// ---------------------------------------------------------------------------
extern "C" void kernel_launch(void* const* d_in, const int* in_sizes, int n_in,
                              void* d_out, int out_size)
{
    (void)in_sizes; (void)n_in; (void)out_size;
    const float* inputs = (const float*)d_in[0];
    const float* W1     = (const float*)d_in[1];
    const float* b1     = (const float*)d_in[2];
    const float* W2     = (const float*)d_in[3];
    const float* b2     = (const float*)d_in[4];
    const float* W_ih   = (const float*)d_in[5];
    const float* W_hh   = (const float*)d_in[6];
    const float* b_ih   = (const float*)d_in[7];
    const float* b_hh   = (const float*)d_in[8];
    const float* W3     = (const float*)d_in[9];
    const float* b3     = (const float*)d_in[10];
    float* Y = (float*)d_out;

    void *pIq, *pX1q, *pX2q, *pGX, *pH, *pW1, *pW2, *pWi;
    cudaGetSymbolAddress(&pIq,  gIq);
    cudaGetSymbolAddress(&pX1q, gX1q);
    cudaGetSymbolAddress(&pX2q, gX2q);
    cudaGetSymbolAddress(&pGX,  gGX);
    cudaGetSymbolAddress(&pH,   gHout);
    cudaGetSymbolAddress(&pW1,  gW1q);
    cudaGetSymbolAddress(&pW2,  gW2q);
    cudaGetSymbolAddress(&pWi,  gWiq);

    cudaFuncSetAttribute(mma_gemm<0>, cudaFuncAttributeMaxDynamicSharedMemorySize, GEMM_SMEM);
    cudaFuncSetAttribute(mma_gemm<1>, cudaFuncAttributeMaxDynamicSharedMemorySize, GEMM_SMEM);
    cudaFuncSetAttribute(lstm_scan, cudaFuncAttributeMaxDynamicSharedMemorySize, SCAN_SMEM);

    // Weight quant + scan prepack (once)
    quant_f16<<<H_DIM * IN_DIM / 4 / 256, 256>>>(W1, (__half*)pW1, H_DIM * IN_DIM / 4);
    quant_f16<<<H4 * H_DIM / 4 / 256, 256>>>(W2, (__half*)pW2, H4 * H_DIM / 4);
    quant_f16<<<GATES * H4 / 4 / 256, 256>>>(W_ih, (__half*)pWi, GATES * H4 / 4);
    prepack_whh<<<(40 * GATES + 255) / 256, 256>>>(W_hh);

    // Chunked batch-parallel pipeline: input quant -> fc1 -> fc2 -> gates
    for (int c = 0; c < MTOT / CHUNK; ++c) {
        const float* Ain = inputs + (size_t)c * CHUNK * IN_DIM;
        quant_f16<<<(long)CHUNK * IN_DIM / 4 / 256, 256>>>(Ain,
            (__half*)pIq, (long)CHUNK * IN_DIM / 4);

        mma_gemm<1><<<dim3(H_DIM / 64, CHUNK / 256), 256, GEMM_SMEM>>>(
            (__half*)pIq, (__half*)pW1, b1, nullptr,
            (__half*)pX1q, H_DIM, IN_DIM);

        mma_gemm<1><<<dim3(H4 / 64, CHUNK / 256), 256, GEMM_SMEM>>>(
            (__half*)pX1q, (__half*)pW2, b2, nullptr,
            (__half*)pX2q, H4, H_DIM);

        mma_gemm<0><<<dim3(GATES / 64, CHUNK / 256), 256, GEMM_SMEM>>>(
            (__half*)pX2q, (__half*)pWi, b_ih, b_hh,
            (__half*)pGX + (size_t)c * CHUNK * GATES, GATES, H4);
    }

    // Recurrence + output projection
    lstm_scan<<<BATCH / 2, GATES, SCAN_SMEM>>>((__half*)pGX, (float*)pH);
    out_gemv<<<MTOT / 8, 256>>>((float*)pH, W3, b3, Y);
}

// round 17
// speedup vs baseline: 1.4169x; 1.0168x over previous
#include <cuda_runtime.h>
#include <cuda_fp16.h>
#include <cstdint>
#include <cstddef>

// ---------------------------------------------------------------------------
// Problem constants
// ---------------------------------------------------------------------------
#define T_STEPS 2048
#define BATCH   256
#define IN_DIM  64
#define H_DIM   1280
#define H4      320
#define HID     160
#define GATES   640
#define O_DIM   32
#define MTOT    (T_STEPS*BATCH)   // 524288
#define CHUNK   131072            // rows per pipeline chunk (4 chunks)

// ---------------------------------------------------------------------------
// Device scratch (activations/GX/weights all fp16) — ~1.4GB total
// ---------------------------------------------------------------------------
__device__ __align__(256) __half gIq [(size_t)CHUNK * IN_DIM];   // 16.8MB
__device__ __align__(256) __half gX1q[(size_t)CHUNK * H_DIM];    // 336MB
__device__ __align__(256) __half gX2q[(size_t)CHUNK * H4];       // 84MB
__device__ __align__(256) __half gGX [(size_t)MTOT * GATES];     // 671MB
__device__ __align__(256) float gHout[(size_t)MTOT * HID];       // 335MB
__device__ __align__(256) __half gW1q[H_DIM * IN_DIM];
__device__ __align__(256) __half gW2q[H4 * H_DIM];
__device__ __align__(256) __half gWiq[GATES * H4];
__device__ __align__(256) uint2 gWt2[40 * GATES];   // W_hh fp16 pack for scan

// ---------------------------------------------------------------------------
// PTX helpers — base-ISA only (sm_80+ features, legal on .target sm_103)
// ---------------------------------------------------------------------------
__device__ __forceinline__ uint32_t smem_u32(const void* p) {
    uint32_t a;
    asm("{ .reg .u64 t; cvta.to.shared.u64 t, %1; cvt.u32.u64 %0, t; }"
        : "=r"(a) : "l"(p));
    return a;
}
__device__ __forceinline__ void cp_async16(uint32_t dst, const void* src) {
    asm volatile("cp.async.cg.shared.global [%0], [%1], 16;"
                 :: "r"(dst), "l"(src) : "memory");
}
#define CP_COMMIT() asm volatile("cp.async.commit_group;" ::: "memory")
#define CP_WAIT(n)  asm volatile("cp.async.wait_group %0;" :: "n"(n) : "memory")

__device__ __forceinline__ void ldsm_x4(uint32_t* r, uint32_t addr) {
    asm volatile("ldmatrix.sync.aligned.m8n8.x4.shared.b16 {%0,%1,%2,%3}, [%4];"
        : "=r"(r[0]), "=r"(r[1]), "=r"(r[2]), "=r"(r[3]) : "r"(addr));
}
__device__ __forceinline__ void mma16816(float* d, const uint32_t* a,
                                         const uint32_t* b) {
    asm volatile("mma.sync.aligned.m16n8k16.row.col.f32.f16.f16.f32 "
        "{%0,%1,%2,%3}, {%4,%5,%6,%7}, {%8,%9}, {%0,%1,%2,%3};"
        : "+f"(d[0]), "+f"(d[1]), "+f"(d[2]), "+f"(d[3])
        : "r"(a[0]), "r"(a[1]), "r"(a[2]), "r"(a[3]), "r"(b[0]), "r"(b[1]));
}

// ---------------------------------------------------------------------------
// SMEM: CTA tile 256x64, BK=32, 8 warps (4M x 2N), warp tile 64x32.
// THREE pipeline stages, buf s at s*20480:
//   A [256][32]f16 @+0 (16K), B [64][32]f16 @+16384 (4K)
// Swizzle: 16B chunk c (0..3) of a 64B row -> c ^ ((row>>1)&3).
// ---------------------------------------------------------------------------
#define BUF_STRIDE 20480
#define SM_B       16384
#define GEMM_SMEM  (3 * BUF_STRIDE)     // 61440

template <int ACT>   // 1: leaky_relu; 0: plain (+bias2)  — both write fp16
__global__ __launch_bounds__(256, 2)
void mma_gemm(const __half* __restrict__ Aq, const __half* __restrict__ Bq,
              const float* __restrict__ bias, const float* __restrict__ bias2,
              __half* __restrict__ outQ, int N, int K)
{
    extern __shared__ __align__(128) char smem[];
    const uint32_t sbase = smem_u32(smem);
    const int tid  = threadIdx.x;
    const int lane = tid & 31;
    const int w    = tid >> 5;
    const int warpM = w & 3;        // 0..3 -> M rows [warpM*64, +64)
    const int warpN = w >> 2;       // 0..1 -> N cols [warpN*32, +32)
    const int m0 = blockIdx.y * 256;
    const int n0 = blockIdx.x * 64;

    float acc[4][4][4];
#pragma unroll
    for (int mt = 0; mt < 4; ++mt)
#pragma unroll
        for (int nt = 0; nt < 4; ++nt)
#pragma unroll
            for (int r = 0; r < 4; ++r) acc[mt][nt][r] = 0.f;

    const int NK = K >> 5;

    // A ldmatrix offsets (proven layout)
    uint32_t offA[4][2], offB[2][2];
#pragma unroll
    for (int mt = 0; mt < 4; ++mt)
#pragma unroll
        for (int s = 0; s < 2; ++s) {
            int row = warpM * 64 + mt * 16 + (lane & 15);
            int ch  = s * 2 + (lane >> 4);
            offA[mt][s] = row * 64 + ((ch ^ ((row >> 1) & 3)) << 4);
        }
    // B ldmatrix offsets (non-trans; [N][K] smem; proven layout)
#pragma unroll
    for (int nh = 0; nh < 2; ++nh)
#pragma unroll
        for (int s = 0; s < 2; ++s) {
            int g   = lane >> 3;
            int row = warpN * 32 + nh * 16 + ((g >> 1) << 3) + (lane & 7);
            int ch  = s * 2 + (g & 1);
            offB[nh][s] = SM_B + row * 64 + ((ch ^ ((row >> 1) & 3)) << 4);
        }

    auto issue_load = [&](int kt, int buf) {
        const uint32_t bb = sbase + (uint32_t)buf * BUF_STRIDE;
        const size_t kof = (size_t)kt * 32;
#pragma unroll
        for (int j = 0; j < 4; ++j) {           // A: 1024 16B-chunks
            int i = tid + j * 256;
            int row = i >> 2, c = i & 3;
            const __half* src = Aq + (size_t)(m0 + row) * K + kof + c * 8;
            uint32_t dst = bb + row * 64 + ((c ^ ((row >> 1) & 3)) << 4);
            cp_async16(dst, src);
        }
        {                                        // B: 256 16B-chunks
            int row = tid >> 2, c = tid & 3;
            const __half* src = Bq + (size_t)(n0 + row) * K + kof + c * 8;
            uint32_t dst = bb + SM_B + row * 64 + ((c ^ ((row >> 1) & 3)) << 4);
            cp_async16(dst, src);
        }
        CP_COMMIT();
    };

    // Prime two stages
    issue_load(0, 0);
    if (NK > 1) issue_load(1, 1); else CP_COMMIT();

    int bc = 0;      // consume buffer
    int bi = 2;      // issue buffer (for kt+2)
    for (int kt = 0; kt < NK; ++kt) {
        CP_WAIT(1);                 // load(kt) complete (FIFO retirement)
        __syncthreads();            // all warps' loads visible; buf (kt+2)%3 free

        if (kt + 2 < NK) {
            issue_load(kt + 2, bi);
            bi = (bi == 2) ? 0 : bi + 1;
        } else {
            CP_COMMIT();            // empty group keeps FIFO count exact
        }

        const uint32_t bb = sbase + (uint32_t)bc * BUF_STRIDE;
#pragma unroll
        for (int s = 0; s < 2; ++s) {
            uint32_t a[4][4], bh[4][2];
#pragma unroll
            for (int mt = 0; mt < 4; ++mt)
                ldsm_x4(a[mt], bb + offA[mt][s]);
#pragma unroll
            for (int nh = 0; nh < 2; ++nh) {
                uint32_t t[4];
                ldsm_x4(t, bb + offB[nh][s]);
                bh[nh*2][0]   = t[0]; bh[nh*2][1]   = t[1];
                bh[nh*2+1][0] = t[2]; bh[nh*2+1][1] = t[3];
            }
#pragma unroll
            for (int mt = 0; mt < 4; ++mt)
#pragma unroll
                for (int nt = 0; nt < 4; ++nt)
                    mma16816(acc[mt][nt], a[mt], bh[nt]);
        }
        bc = (bc == 2) ? 0 : bc + 1;
    }

    // ---------------- Epilogue: direct half2 stores from fragments ---------
    const int cbase = n0 + warpN * 32 + (lane & 3) * 2;
    float bv0[4], bv1[4];
#pragma unroll
    for (int nt = 0; nt < 4; ++nt) {
        int c = cbase + nt * 8;
        bv0[nt] = bias[c]     + (bias2 ? bias2[c]     : 0.f);
        bv1[nt] = bias[c + 1] + (bias2 ? bias2[c + 1] : 0.f);
    }
#pragma unroll
    for (int mt = 0; mt < 4; ++mt) {
        int r = m0 + warpM * 64 + mt * 16 + (lane >> 2);
#pragma unroll
        for (int nt = 0; nt < 4; ++nt) {
            int c = cbase + nt * 8;
            float v0 = acc[mt][nt][0] + bv0[nt];
            float v1 = acc[mt][nt][1] + bv1[nt];
            float v2 = acc[mt][nt][2] + bv0[nt];
            float v3 = acc[mt][nt][3] + bv1[nt];
            if (ACT) {
                v0 = (v0 > 0.f) ? v0 : 0.01f * v0;
                v1 = (v1 > 0.f) ? v1 : 0.01f * v1;
                v2 = (v2 > 0.f) ? v2 : 0.01f * v2;
                v3 = (v3 > 0.f) ? v3 : 0.01f * v3;
            }
            __half2 q0 = __floats2half2_rn(v0, v1);
            __half2 q1 = __floats2half2_rn(v2, v3);
            *(uint32_t*)(outQ + (size_t)r * N + c)       = *(uint32_t*)&q0;
            *(uint32_t*)(outQ + (size_t)(r + 8) * N + c) = *(uint32_t*)&q1;
        }
    }
}

// ---------------------------------------------------------------------------
// fp32 -> fp16 quant (weights and activations)
// ---------------------------------------------------------------------------
__global__ void quant_f16(const float* __restrict__ src,
                          __half* __restrict__ dst, long n4)
{
    long i = (long)blockIdx.x * 256 + threadIdx.x;
    if (i >= n4) return;
    float4 v = ((const float4*)src)[i];
    __half h[4] = { __float2half_rn(v.x), __float2half_rn(v.y),
                    __float2half_rn(v.z), __float2half_rn(v.w) };
    *(uint2*)(dst + i * 4) = *(uint2*)h;
}

// ---------------------------------------------------------------------------
// Scan prep + scan + output GEMV
// ---------------------------------------------------------------------------
__device__ __forceinline__ float2 ffma2(float2 a, float2 b, float2 c) {
    float2 d;
    asm("fma.rn.f32x2 %0, %1, %2, %3;"
        : "=l"(reinterpret_cast<unsigned long long&>(d))
        : "l"(reinterpret_cast<unsigned long long&>(a)),
          "l"(reinterpret_cast<unsigned long long&>(b)),
          "l"(reinterpret_cast<unsigned long long&>(c)));
    return d;
}
__device__ __forceinline__ float fast_sigmoid(float x) {
    return __fdividef(1.f, 1.f + __expf(-x));
}
__device__ __forceinline__ float fast_tanh(float x) {
    return 1.f - __fdividef(2.f, __expf(2.f * x) + 1.f);
}

__global__ void prepack_whh(const float* __restrict__ W)
{
    int i = blockIdx.x * 256 + threadIdx.x;
    if (i >= 40 * GATES) return;
    int p = i / GATES, g = i % GATES;
    const float* wr = W + (size_t)g * HID + p * 4;
    __half2 h01 = __floats2half2_rn(wr[0], wr[1]);
    __half2 h23 = __floats2half2_rn(wr[2], wr[3]);
    uint2 v;
    v.x = *reinterpret_cast<uint32_t*>(&h01);
    v.y = *reinterpret_cast<uint32_t*>(&h23);
    gWt2[(size_t)p * GATES + g] = v;
}

#define SCAN_SMEM (40 * GATES * 8 + 2 * HID * 4 + 2 * GATES * 4)

__global__ __launch_bounds__(GATES, 1)
void lstm_scan(const __half* __restrict__ GX, float* __restrict__ Hout)
{
    extern __shared__ unsigned char smem_raw[];
    uint2* sW = reinterpret_cast<uint2*>(smem_raw);
    float* sH = reinterpret_cast<float*>(smem_raw + 40 * GATES * 8);
    float* sG = sH + 2 * HID;

    const int tid  = threadIdx.x;
    const int g    = tid;
    const int row0 = blockIdx.x * 2;

    for (int i = tid; i < 40 * GATES; i += GATES) sW[i] = gWt2[i];
    if (tid < 2 * HID) sH[tid] = 0.f;

    float cc = 0.f;
    const int cr = tid < 2 * HID ? (tid / HID) : 0;
    const int cj = tid < 2 * HID ? (tid - cr * HID) : 0;

    __syncthreads();

    // Prefetch t=0 gate pre-activations
    size_t base = (size_t)row0 * GATES;
    __half pre0 = GX[base + g];
    __half pre1 = GX[base + GATES + g];

    for (int t = 0; t < T_STEPS; ++t) {
        float gx0 = __half2float(pre0);
        float gx1 = __half2float(pre1);
        // Prefetch t+1 (latency hidden behind the 40-iter dot product)
        if (t + 1 < T_STEPS) {
            size_t nb = (size_t)(t + 1) * (BATCH * GATES) + (size_t)row0 * GATES;
            pre0 = GX[nb + g];
            pre1 = GX[nb + GATES + g];
        }

        float2 acc0 = make_float2(0.f, 0.f);
        float2 acc1 = make_float2(0.f, 0.f);
#pragma unroll
        for (int p = 0; p < 40; ++p) {
            uint2 w = sW[p * GATES + g];
            float2 wA = __half22float2(*reinterpret_cast<__half2*>(&w.x));
            float2 wB = __half22float2(*reinterpret_cast<__half2*>(&w.y));
            float4 h0v = *reinterpret_cast<const float4*>(&sH[p * 4]);
            float4 h1v = *reinterpret_cast<const float4*>(&sH[HID + p * 4]);
            acc0 = ffma2(wA, make_float2(h0v.x, h0v.y), acc0);
            acc0 = ffma2(wB, make_float2(h0v.z, h0v.w), acc0);
            acc1 = ffma2(wA, make_float2(h1v.x, h1v.y), acc1);
            acc1 = ffma2(wB, make_float2(h1v.z, h1v.w), acc1);
        }
        float p0 = acc0.x + acc0.y + gx0;
        float p1 = acc1.x + acc1.y + gx1;

        float a0, a1;
        if (g >= 320 && g < 480) { a0 = fast_tanh(p0);    a1 = fast_tanh(p1);    }
        else                     { a0 = fast_sigmoid(p0); a1 = fast_sigmoid(p1); }
        sG[g] = a0;
        sG[GATES + g] = a1;
        __syncthreads();

        if (tid < 2 * HID) {
            const float* Gr = sG + cr * GATES;
            float iv = Gr[cj], fv = Gr[HID + cj], gv = Gr[2 * HID + cj], ov = Gr[3 * HID + cj];
            cc = fv * cc + iv * gv;
            float hv = ov * fast_tanh(cc);
            sH[cr * HID + cj] = hv;
            Hout[(size_t)t * (BATCH * HID) + (size_t)(row0 + cr) * HID + cj] = hv;
        }
        __syncthreads();
    }
}

__global__ __launch_bounds__(256)
void out_gemv(const float* __restrict__ H, const float* __restrict__ W3,
              const float* __restrict__ b3, float* __restrict__ Y)
{
    __shared__ float sW[HID * O_DIM];
    __shared__ float sHr[8 * HID];

    const int tid = threadIdx.x;
    const int r   = tid >> 5;
    const int o   = tid & 31;

    for (int i = tid; i < HID * O_DIM; i += 256) {
        int k = i >> 5, oo = i & 31;
        sW[i] = W3[(size_t)oo * HID + k];
    }
    const size_t mrow0 = (size_t)blockIdx.x * 8;
    for (int i = tid; i < 8 * HID; i += 256)
        sHr[i] = H[mrow0 * HID + i];
    __syncthreads();

    float acc = b3[o];
#pragma unroll 8
    for (int k = 0; k < HID; ++k)
        acc = fmaf(sHr[r * HID + k], sW[k * O_DIM + o], acc);
    Y[(mrow0 + r) * O_DIM + o] = acc;
}

// ---------------------------------------------------------------------------
// Launch
// ---------------------------------------------------------------------------
extern "C" void kernel_launch(void* const* d_in, const int* in_sizes, int n_in,
                              void* d_out, int out_size)
{
    (void)in_sizes; (void)n_in; (void)out_size;
    const float* inputs = (const float*)d_in[0];
    const float* W1     = (const float*)d_in[1];
    const float* b1     = (const float*)d_in[2];
    const float* W2     = (const float*)d_in[3];
    const float* b2     = (const float*)d_in[4];
    const float* W_ih   = (const float*)d_in[5];
    const float* W_hh   = (const float*)d_in[6];
    const float* b_ih   = (const float*)d_in[7];
    const float* b_hh   = (const float*)d_in[8];
    const float* W3     = (const float*)d_in[9];
    const float* b3     = (const float*)d_in[10];
    float* Y = (float*)d_out;

    void *pIq, *pX1q, *pX2q, *pGX, *pH, *pW1, *pW2, *pWi;
    cudaGetSymbolAddress(&pIq,  gIq);
    cudaGetSymbolAddress(&pX1q, gX1q);
    cudaGetSymbolAddress(&pX2q, gX2q);
    cudaGetSymbolAddress(&pGX,  gGX);
    cudaGetSymbolAddress(&pH,   gHout);
    cudaGetSymbolAddress(&pW1,  gW1q);
    cudaGetSymbolAddress(&pW2,  gW2q);
    cudaGetSymbolAddress(&pWi,  gWiq);

    cudaFuncSetAttribute(mma_gemm<0>, cudaFuncAttributeMaxDynamicSharedMemorySize, GEMM_SMEM);
    cudaFuncSetAttribute(mma_gemm<1>, cudaFuncAttributeMaxDynamicSharedMemorySize, GEMM_SMEM);
    cudaFuncSetAttribute(lstm_scan, cudaFuncAttributeMaxDynamicSharedMemorySize, SCAN_SMEM);

    // Weight quant + scan prepack (once)
    quant_f16<<<H_DIM * IN_DIM / 4 / 256, 256>>>(W1, (__half*)pW1, H_DIM * IN_DIM / 4);
    quant_f16<<<H4 * H_DIM / 4 / 256, 256>>>(W2, (__half*)pW2, H4 * H_DIM / 4);
    quant_f16<<<GATES * H4 / 4 / 256, 256>>>(W_ih, (__half*)pWi, GATES * H4 / 4);
    prepack_whh<<<(40 * GATES + 255) / 256, 256>>>(W_hh);

    // Chunked batch-parallel pipeline: input quant -> fc1 -> fc2 -> gates
    for (int c = 0; c < MTOT / CHUNK; ++c) {
        const float* Ain = inputs + (size_t)c * CHUNK * IN_DIM;
        quant_f16<<<(long)CHUNK * IN_DIM / 4 / 256, 256>>>(Ain,
            (__half*)pIq, (long)CHUNK * IN_DIM / 4);

        mma_gemm<1><<<dim3(H_DIM / 64, CHUNK / 256), 256, GEMM_SMEM>>>(
            (__half*)pIq, (__half*)pW1, b1, nullptr,
            (__half*)pX1q, H_DIM, IN_DIM);

        mma_gemm<1><<<dim3(H4 / 64, CHUNK / 256), 256, GEMM_SMEM>>>(
            (__half*)pX1q, (__half*)pW2, b2, nullptr,
            (__half*)pX2q, H4, H_DIM);

        mma_gemm<0><<<dim3(GATES / 64, CHUNK / 256), 256, GEMM_SMEM>>>(
            (__half*)pX2q, (__half*)pWi, b_ih, b_hh,
            (__half*)pGX + (size_t)c * CHUNK * GATES, GATES, H4);
    }

    // Recurrence + output projection
    lstm_scan<<<BATCH / 2, GATES, SCAN_SMEM>>>((__half*)pGX, (float*)pH);
    out_gemv<<<MTOT / 8, 256>>>((float*)pH, W3, b3, Y);
}